// round 5
// baseline (speedup 1.0000x reference)
#include <cuda_runtime.h>

typedef unsigned long long ull;

__device__ __forceinline__ ull dup2(float x) {
    ull r; asm("mov.b64 %0, {%1, %1};" : "=l"(r) : "f"(x)); return r;
}
__device__ __forceinline__ void fma2(ull& d, ull a, ull b) {
    asm("fma.rn.f32x2 %0, %1, %2, %0;" : "+l"(d) : "l"(a), "l"(b));
}
__device__ __forceinline__ void add2(ull& d, ull a) {
    asm("add.rn.f32x2 %0, %0, %1;" : "+l"(d) : "l"(a));
}
__device__ __forceinline__ void unpk(ull v, float& lo, float& hi) {
    asm("mov.b64 {%0, %1}, %2;" : "=f"(lo), "=f"(hi) : "l"(v));
}

#define BSZ 128
#define FCK 25281
#define SK  37

// scratch (no allocs allowed -> __device__ globals). All intermediates are
// B-fastest ("HWB") so every gather/scatter is a coalesced 128-float row.
__device__ float g_y0[220 * 220 * BSZ];     // layer0 relu map [pos][b]
__device__ float g_p0s[3025 * BSZ];         // per-conv0-block per-b sum
__device__ float g_p0ss[3025 * BSZ];        // per-conv0-block per-b sumsq
__device__ float g_m0[BSZ], g_r0[BSZ];      // mean / rstd (split tables)
__device__ float g_h1[110 * 110 * BSZ];     // pooled [pos][b]
__device__ float g_y1[159 * 159 * BSZ];     // layer1 relu map [pos][b]
__device__ float g_p1s[2809 * BSZ];
__device__ float g_p1ss[2809 * BSZ];
__device__ float g_m1[BSZ], g_r1[BSZ];
__device__ float g_part[SK * BSZ * 1000];   // split-K partial logits

// ---------------------------------------------------------------------------
// conv0: local conv 3x8x8 stride 4, 16 oc, + bias + relu, HWB scatter,
// fused per-block LN partial sums.
// grid (55,55), 256 threads (8 warps), 4-way split-K (48 k per quarter).
// dyn smem = (3072 + 192*128 + 512)*4 = 112640 B  -> 2 blocks/SM, 16 warps/SM
// thread tile: 4 batches x 8 oc x 48 k  (oc packed in f32x2)
// ---------------------------------------------------------------------------
__global__ void __launch_bounds__(256) conv0_kernel(const float* __restrict__ x,
                                                    const float* __restrict__ w0,
                                                    const float* __restrict__ b0) {
    extern __shared__ float sm[];
    float* Ws   = sm;                    // [192][16] k-major, oc fast
    float* P2   = sm + 3072;             // [192][128] k-major, b fast
    float* Ssum = sm + 3072 + 192 * 128; // [2][128]
    float* Sss  = Ssum + 256;            // [2][128]
    const int i = blockIdx.x, j = blockIdx.y;
    const int t = threadIdx.x;

    // weights -> smem transposed
    const float* wloc = w0 + (i * 55 + j) * 3072;
    for (int e = t; e < 3072; e += 256) {
        int oc = e / 192, k = e - oc * 192;
        Ws[k * 16 + oc] = wloc[e];
    }
    // patches -> smem k-major (float4 over dj quads; lanes vary b)
    for (int e = t; e < 6144; e += 256) {
        int b = e & 127, kq = e >> 7;
        int c = kq >> 4, di = (kq >> 1) & 7, djq = kq & 1;
        float4 v = *(const float4*)&x[((b * 3 + c) * 224 + (i * 4 + di)) * 224
                                      + j * 4 + djq * 4];
        int k = kq * 4;
        P2[(k + 0) * 128 + b] = v.x;
        P2[(k + 1) * 128 + b] = v.y;
        P2[(k + 2) * 128 + b] = v.z;
        P2[(k + 3) * 128 + b] = v.w;
    }
    __syncthreads();

    const int bg = t & 31;               // 4-batch group
    const int half = (t >> 5) & 1;       // oc 0-7 / 8-15  (uniform per warp)
    const int kq = t >> 6;               // k quarter (48 k each)
    const float* Wh = Ws + half * 8;
    ull acc[4][4];
#pragma unroll
    for (int p = 0; p < 4; p++)
#pragma unroll
        for (int q = 0; q < 4; q++) acc[p][q] = 0ull;

    const int kbase = kq * 48;
#pragma unroll 4
    for (int k = 0; k < 48; k++) {
        int kk = kbase + k;
        float4 xq = *(const float4*)&P2[kk * 128 + bg * 4];
        const ull* wp = (const ull*)&Wh[kk * 16];
        ull w0v = wp[0], w1v = wp[1], w2v = wp[2], w3v = wp[3];
        ull x0 = dup2(xq.x), x1 = dup2(xq.y), x2 = dup2(xq.z), x3 = dup2(xq.w);
        fma2(acc[0][0], x0, w0v); fma2(acc[1][0], x0, w1v);
        fma2(acc[2][0], x0, w2v); fma2(acc[3][0], x0, w3v);
        fma2(acc[0][1], x1, w0v); fma2(acc[1][1], x1, w1v);
        fma2(acc[2][1], x1, w2v); fma2(acc[3][1], x1, w3v);
        fma2(acc[0][2], x2, w0v); fma2(acc[1][2], x2, w1v);
        fma2(acc[2][2], x2, w2v); fma2(acc[3][2], x2, w3v);
        fma2(acc[0][3], x3, w0v); fma2(acc[1][3], x3, w1v);
        fma2(acc[2][3], x3, w2v); fma2(acc[3][3], x3, w3v);
    }

    // combine 4 k-quarters: quarters 1..3 dump accs into (dead) patch smem.
    __syncthreads();
    ull* red = (ull*)P2;                 // [3][16][64]
    const int slot = t & 63;
    if (kq >= 1) {
#pragma unroll
        for (int p = 0; p < 4; p++)
#pragma unroll
            for (int q = 0; q < 4; q++)
                red[((kq - 1) * 16 + p * 4 + q) * 64 + slot] = acc[p][q];
    }
    __syncthreads();

    if (kq == 0) {
#pragma unroll
        for (int p = 0; p < 4; p++)
#pragma unroll
            for (int q = 0; q < 4; q++) {
                int pq = p * 4 + q;
                add2(acc[p][q], red[pq * 64 + slot]);
                add2(acc[p][q], red[(16 + pq) * 64 + slot]);
                add2(acc[p][q], red[(32 + pq) * 64 + slot]);
            }

        float bias[8];
#pragma unroll
        for (int r = 0; r < 8; r++) bias[r] = b0[((half * 8 + r) * 55 + i) * 55 + j];

#pragma unroll
        for (int q = 0; q < 4; q++) {
            int b = bg * 4 + q;
            float s = 0.f, ss = 0.f;
#pragma unroll
            for (int p = 0; p < 4; p++) {
                float lo, hi; unpk(acc[p][q], lo, hi);
                int oc0 = half * 8 + 2 * p, oc1 = oc0 + 1;
                float v0 = fmaxf(lo + bias[2 * p], 0.f);
                float v1 = fmaxf(hi + bias[2 * p + 1], 0.f);
                g_y0[((i * 4 + (oc0 >> 2)) * 220 + (j * 4 + (oc0 & 3))) * 128 + b] = v0;
                g_y0[((i * 4 + (oc1 >> 2)) * 220 + (j * 4 + (oc1 & 3))) * 128 + b] = v1;
                s += v0 + v1;
                ss = fmaf(v0, v0, ss);
                ss = fmaf(v1, v1, ss);
            }
            Ssum[half * 128 + b] = s;
            Sss[half * 128 + b]  = ss;
        }
    }
    __syncthreads();
    if (t < 32) {
        int blk = blockIdx.y * 55 + blockIdx.x;
        for (int b = t; b < 128; b += 32) {
            g_p0s[blk * 128 + b]  = Ssum[b] + Ssum[128 + b];
            g_p0ss[blk * 128 + b] = Sss[b] + Sss[128 + b];
        }
    }
}

// ---------------------------------------------------------------------------
// reduce per-block LN partials -> mean, rstd. grid 128 (one block per image)
// ---------------------------------------------------------------------------
__global__ void ln2_kernel(int which) {
    const float* ps  = which ? g_p1s  : g_p0s;
    const float* pss = which ? g_p1ss : g_p0ss;
    float* gm        = which ? g_m1 : g_m0;
    float* gr        = which ? g_r1 : g_r0;
    const int nblk   = which ? 2809 : 3025;
    const float invn = which ? (1.f / 25281.f) : (1.f / 48400.f);
    int b = blockIdx.x, t = threadIdx.x;
    float s = 0.f, ss = 0.f;
    for (int k = t; k < nblk; k += 256) {
        s  += ps[k * 128 + b];
        ss += pss[k * 128 + b];
    }
    __shared__ float r1[8], r2[8];
    for (int o = 16; o; o >>= 1) {
        s  += __shfl_xor_sync(0xffffffffu, s, o);
        ss += __shfl_xor_sync(0xffffffffu, ss, o);
    }
    if ((t & 31) == 0) { r1[t >> 5] = s; r2[t >> 5] = ss; }
    __syncthreads();
    if (t == 0) {
        s = 0.f; ss = 0.f;
        for (int w = 0; w < 8; w++) { s += r1[w]; ss += r2[w]; }
        float m = s * invn;
        float var = ss * invn - m * m;
        gm[b] = m;
        gr[b] = rsqrtf(var + 1e-5f);
    }
}

// ---------------------------------------------------------------------------
// normalize (layer0) + 2x2 maxpool -> g_h1 [pos][b]  (all coalesced)
// ---------------------------------------------------------------------------
__global__ void norm_pool_kernel(const float* __restrict__ g0,
                                 const float* __restrict__ be0) {
    int idx = blockIdx.x * 256 + threadIdx.x;
    if (idx >= BSZ * 110 * 110) return;
    int b = idx & 127, pos = idx >> 7;
    int r = pos / 110, c = pos - r * 110;
    float m = g_m0[b], rs = g_r0[b];
    float mx = -3.4e38f;
#pragma unroll
    for (int dr = 0; dr < 2; dr++)
#pragma unroll
        for (int dc = 0; dc < 2; dc++) {
            int P = (2 * r + dr) * 220 + 2 * c + dc;
            float v = (g_y0[P * 128 + b] - m) * rs * g0[P] + be0[P];
            mx = fmaxf(mx, v);
        }
    g_h1[pos * 128 + b] = mx;
}

// ---------------------------------------------------------------------------
// conv1: local conv 1x6x6 stride 2, 9 oc (packed), + bias + relu, HWB scatter,
// fused LN partials. grid (53,53), 128 threads (1 batch each).  [R3 proven]
// ---------------------------------------------------------------------------
__global__ void conv1_kernel(const float* __restrict__ w1,
                             const float* __restrict__ b1) {
    __shared__ float Ws2[36 * 10];       // [k][oc] padded to 10 (8B-aligned pairs)
    __shared__ float P2[36 * 128];       // [k][b]
    int i = blockIdx.x, j = blockIdx.y, t = threadIdx.x;
    const float* wloc = w1 + (i * 53 + j) * 324;
    for (int e = t; e < 324; e += 128) {
        int oc = e / 36, k = e - oc * 36;
        Ws2[k * 10 + oc] = wloc[e];
    }
    for (int e = t; e < 36 * 128; e += 128) {
        int b = e & 127, kk = e >> 7;
        int di = kk / 6, dj = kk - di * 6;
        P2[kk * 128 + b] = g_h1[((2 * i + di) * 110 + 2 * j + dj) * 128 + b];
    }
    __syncthreads();

    ull a[4] = {0ull, 0ull, 0ull, 0ull};
    float a8 = 0.f;
#pragma unroll 4
    for (int k = 0; k < 36; k++) {
        float xv = P2[k * 128 + t];
        ull xd = dup2(xv);
        const ull* wp = (const ull*)&Ws2[k * 10];
        fma2(a[0], xd, wp[0]);
        fma2(a[1], xd, wp[1]);
        fma2(a[2], xd, wp[2]);
        fma2(a[3], xd, wp[3]);
        a8 = fmaf(xv, Ws2[k * 10 + 8], a8);
    }
    float v[9];
    unpk(a[0], v[0], v[1]); unpk(a[1], v[2], v[3]);
    unpk(a[2], v[4], v[5]); unpk(a[3], v[6], v[7]);
    v[8] = a8;
    float s = 0.f, ss = 0.f;
#pragma unroll
    for (int oc = 0; oc < 9; oc++) {
        float val = fmaxf(v[oc] + b1[(oc * 53 + i) * 53 + j], 0.f);
        int row = i * 3 + oc / 3, col = j * 3 + oc % 3;
        g_y1[(row * 159 + col) * 128 + t] = val;
        s += val;
        ss = fmaf(val, val, ss);
    }
    int blk = blockIdx.y * 53 + blockIdx.x;
    g_p1s[blk * 128 + t]  = s;
    g_p1ss[blk * 128 + t] = ss;
}

// ---------------------------------------------------------------------------
// FC with FUSED layer-1 layernorm in the F-tile load:
// feat[k][b] = (y1[k][b] - m1[b]) * r1[b] * g1[k] + be1[k]   (on the fly)
// logits_part[sk][b][n] = sum_{k in chunk} feat[k][b] * fcw[n][k]
// grid (8, SK), 256 threads; Btile=128, Ntile=128, KT=32; 8b x 8n per thread
// ---------------------------------------------------------------------------
__global__ void fc_kernel(const float* __restrict__ fcw,
                          const float* __restrict__ g1,
                          const float* __restrict__ be1) {
    __shared__ float Fs[32 * 128];
    __shared__ float Wsm[32 * 128];
    int t = threadIdx.x;
    int nblk = blockIdx.x, sk = blockIdx.y;
    int kbeg = (int)((long long)FCK * sk / SK);
    int kend = (int)((long long)FCK * (sk + 1) / SK);
    int tb = t & 15, tn = t >> 4;
    int nbase = nblk * 128;

    ull acc[8][4];
#pragma unroll
    for (int r = 0; r < 8; r++)
#pragma unroll
        for (int q = 0; q < 4; q++) acc[r][q] = 0ull;

    for (int k0 = kbeg; k0 < kend; k0 += 32) {
        // F tile: float4 over b, normalized on the fly (swizzle-compatible)
#pragma unroll
        for (int p = 0; p < 4; p++) {
            int g = p * 256 + t;
            int kt = g >> 5, bq = g & 31;
            int k = k0 + kt;
            float4 fv = make_float4(0.f, 0.f, 0.f, 0.f);
            if (k < kend) {
                float4 y = *(const float4*)&g_y1[k * 128 + bq * 4];
                float4 m = *(const float4*)&g_m1[bq * 4];
                float4 r = *(const float4*)&g_r1[bq * 4];
                float gk = g1[k], bk = be1[k];
                fv.x = fmaf((y.x - m.x) * r.x, gk, bk);
                fv.y = fmaf((y.y - m.y) * r.y, gk, bk);
                fv.z = fmaf((y.z - m.z) * r.z, gk, bk);
                fv.w = fmaf((y.w - m.w) * r.w, gk, bk);
            }
            *(float4*)&Fs[(kt << 7) + (((bq ^ kt) & 31) << 2)] = fv;
        }
        // W tile: fcw is [n][k] -> lanes vary k (coalesced scalar; rows odd-len)
#pragma unroll
        for (int e0 = 0; e0 < 4096; e0 += 256) {
            int e = e0 + t;
            int kt = e & 31, row = e >> 5;
            int k = k0 + kt;
            float wv = 0.f;
            int ng = nbase + row;
            if (k < kend && ng < 1000) wv = fcw[ng * FCK + k];
            int sw = (kt << 7) + ((((row >> 2) ^ kt) & 31) << 2) + (row & 3);
            Wsm[sw] = wv;
        }
        __syncthreads();
#pragma unroll 2
        for (int kt = 0; kt < 32; kt++) {
            int base = kt << 7;
            ulonglong2 fA = *(const ulonglong2*)&Fs[base + ((((2 * tb)     ^ kt) & 31) << 2)];
            ulonglong2 fB = *(const ulonglong2*)&Fs[base + ((((2 * tb + 1) ^ kt) & 31) << 2)];
            float4 wA = *(const float4*)&Wsm[base + ((((2 * tn)     ^ kt) & 31) << 2)];
            float4 wB = *(const float4*)&Wsm[base + ((((2 * tn + 1) ^ kt) & 31) << 2)];
            ull wd[8] = {dup2(wA.x), dup2(wA.y), dup2(wA.z), dup2(wA.w),
                         dup2(wB.x), dup2(wB.y), dup2(wB.z), dup2(wB.w)};
#pragma unroll
            for (int r = 0; r < 8; r++) {
                fma2(acc[r][0], fA.x, wd[r]);
                fma2(acc[r][1], fA.y, wd[r]);
                fma2(acc[r][2], fB.x, wd[r]);
                fma2(acc[r][3], fB.y, wd[r]);
            }
        }
        __syncthreads();
    }

    int b0 = tb * 8;
    float* outp = g_part + sk * (BSZ * 1000);
#pragma unroll
    for (int r = 0; r < 8; r++) {
        int n = nbase + tn * 8 + r;
        if (n >= 1000) continue;
#pragma unroll
        for (int q = 0; q < 4; q++) {
            float lo, hi;
            unpk(acc[r][q], lo, hi);
            outp[(b0 + 2 * q) * 1000 + n] = lo;
            outp[(b0 + 2 * q + 1) * 1000 + n] = hi;
        }
    }
}

// ---------------------------------------------------------------------------
// reduce split-K partials (fixed order -> deterministic) + bias + softmax
// logits kept in smem (no global roundtrip)
// ---------------------------------------------------------------------------
__global__ void softmax_kernel(const float* __restrict__ fcb,
                               float* __restrict__ out) {
    int b = blockIdx.x, t = threadIdx.x;
    __shared__ float lg[1000];
    __shared__ float red[8];
    __shared__ float bc;

    for (int n = t; n < 1000; n += 256) {
        float v = fcb[n];
        for (int s = 0; s < SK; s++) v += g_part[(s * BSZ + b) * 1000 + n];
        lg[n] = v;
    }
    __syncthreads();

    float mx = -3.4e38f;
    for (int n = t; n < 1000; n += 256) mx = fmaxf(mx, lg[n]);
    for (int o = 16; o; o >>= 1) mx = fmaxf(mx, __shfl_xor_sync(0xffffffffu, mx, o));
    if ((t & 31) == 0) red[t >> 5] = mx;
    __syncthreads();
    if (t == 0) {
        float m = red[0];
        for (int w = 1; w < 8; w++) m = fmaxf(m, red[w]);
        bc = m;
    }
    __syncthreads();
    mx = bc;

    float s = 0.f;
    for (int n = t; n < 1000; n += 256) s += expf(lg[n] - mx);
    for (int o = 16; o; o >>= 1) s += __shfl_xor_sync(0xffffffffu, s, o);
    __syncthreads();
    if ((t & 31) == 0) red[t >> 5] = s;
    __syncthreads();
    if (t == 0) {
        float tot = 0.f;
        for (int w = 0; w < 8; w++) tot += red[w];
        bc = 1.f / tot;
    }
    __syncthreads();
    float inv = bc;
    for (int n = t; n < 1000; n += 256)
        out[b * 1000 + n] = expf(lg[n] - mx) * inv;
}

// ---------------------------------------------------------------------------

extern "C" void kernel_launch(void* const* d_in, const int* in_sizes, int n_in,
                              void* d_out, int out_size) {
    const float* x   = (const float*)d_in[0];
    const float* w0  = (const float*)d_in[1];
    const float* b0  = (const float*)d_in[2];
    const float* g0  = (const float*)d_in[3];
    const float* be0 = (const float*)d_in[4];
    const float* w1  = (const float*)d_in[5];
    const float* b1  = (const float*)d_in[6];
    const float* g1  = (const float*)d_in[7];
    const float* be1 = (const float*)d_in[8];
    const float* fcw = (const float*)d_in[9];
    const float* fcb = (const float*)d_in[10];
    float* out = (float*)d_out;

    const int smem0 = (3072 + 192 * 128 + 512) * (int)sizeof(float);  // 112640 B
    cudaFuncSetAttribute(conv0_kernel, cudaFuncAttributeMaxDynamicSharedMemorySize, smem0);

    conv0_kernel<<<dim3(55, 55), 256, smem0>>>(x, w0, b0);
    ln2_kernel<<<128, 256>>>(0);
    norm_pool_kernel<<<(BSZ * 110 * 110 + 255) / 256, 256>>>(g0, be0);
    conv1_kernel<<<dim3(53, 53), 128>>>(w1, b1);
    ln2_kernel<<<128, 256>>>(1);
    fc_kernel<<<dim3(8, SK), 256>>>(fcw, g1, be1);
    softmax_kernel<<<128, 256>>>(fcb, out);
}

// round 6
// speedup vs baseline: 1.1439x; 1.1439x over previous
#include <cuda_runtime.h>

typedef unsigned long long ull;

__device__ __forceinline__ ull dup2(float x) {
    ull r; asm("mov.b64 %0, {%1, %1};" : "=l"(r) : "f"(x)); return r;
}
__device__ __forceinline__ void fma2(ull& d, ull a, ull b) {
    asm("fma.rn.f32x2 %0, %1, %2, %0;" : "+l"(d) : "l"(a), "l"(b));
}
__device__ __forceinline__ void add2(ull& d, ull a) {
    asm("add.rn.f32x2 %0, %0, %1;" : "+l"(d) : "l"(a));
}
__device__ __forceinline__ void unpk(ull v, float& lo, float& hi) {
    asm("mov.b64 {%0, %1}, %2;" : "=f"(lo), "=f"(hi) : "l"(v));
}

#define BSZ 128
#define FCK 25281
#define SK  37

// scratch (no allocs allowed -> __device__ globals). All intermediates are
// B-fastest ("HWB") so every gather/scatter is a coalesced 128-float row.
__device__ float g_y0[220 * 220 * BSZ];     // layer0 relu map [pos][b]
__device__ float g_p0s[3025 * BSZ];         // per-conv0-block per-b sum
__device__ float g_p0ss[3025 * BSZ];        // per-conv0-block per-b sumsq
__device__ float g_m0[BSZ], g_r0[BSZ];      // mean / rstd (split tables)
__device__ float g_h1[110 * 110 * BSZ];     // pooled [pos][b]
__device__ float g_y1[159 * 159 * BSZ];     // layer1 relu map [pos][b]
__device__ float g_p1s[2809 * BSZ];
__device__ float g_p1ss[2809 * BSZ];
__device__ float g_m1[BSZ], g_r1[BSZ];
__device__ float g_feat[FCK * BSZ];         // normalized features [k][b]
__device__ float g_part[SK * BSZ * 1000];   // split-K partial logits

// ---------------------------------------------------------------------------
// conv0: local conv 3x8x8 stride 4, 16 oc, + bias + relu, HWB scatter,
// fused per-block LN partial sums.   [R4-proven form]
// grid (55,55), 128 threads (4 warps -> all 4 SMSPs), split-K over 2 halves.
// dyn smem = (3072 + 192*128 + 512)*4 = 112640 B
// thread tile: 4 batches x 8 oc x 96 k  (oc packed in f32x2)
// ---------------------------------------------------------------------------
__global__ void __launch_bounds__(128) conv0_kernel(const float* __restrict__ x,
                                                    const float* __restrict__ w0,
                                                    const float* __restrict__ b0) {
    extern __shared__ float sm[];
    float* Ws   = sm;                    // [192][16] k-major, oc fast
    float* P2   = sm + 3072;             // [192][128] k-major, b fast
    float* Ssum = sm + 3072 + 192 * 128; // [2][128]
    float* Sss  = Ssum + 256;            // [2][128]
    const int i = blockIdx.x, j = blockIdx.y;
    const int t = threadIdx.x;

    // weights -> smem transposed
    const float* wloc = w0 + (i * 55 + j) * 3072;
    for (int e = t; e < 3072; e += 128) {
        int oc = e / 192, k = e - oc * 192;
        Ws[k * 16 + oc] = wloc[e];
    }
    // patches -> smem k-major (float4 over dj quads; lanes vary b)
    for (int e = t; e < 6144; e += 128) {
        int b = e & 127, kq = e >> 7;
        int c = kq >> 4, di = (kq >> 1) & 7, djq = kq & 1;
        float4 v = *(const float4*)&x[((b * 3 + c) * 224 + (i * 4 + di)) * 224
                                      + j * 4 + djq * 4];
        int k = kq * 4;
        P2[(k + 0) * 128 + b] = v.x;
        P2[(k + 1) * 128 + b] = v.y;
        P2[(k + 2) * 128 + b] = v.z;
        P2[(k + 3) * 128 + b] = v.w;
    }
    __syncthreads();

    const int bg = t & 31;               // 4-batch group
    const int half = (t >> 5) & 1;       // oc 0-7 / 8-15  (uniform per warp)
    const int kh = t >> 6;               // k half (0: k<96, 1: k>=96)
    const float* Wh = Ws + half * 8;
    ull acc[4][4];
#pragma unroll
    for (int p = 0; p < 4; p++)
#pragma unroll
        for (int q = 0; q < 4; q++) acc[p][q] = 0ull;

    const int kbase = kh * 96;
#pragma unroll 4
    for (int k = 0; k < 96; k++) {
        int kk = kbase + k;
        float4 xq = *(const float4*)&P2[kk * 128 + bg * 4];
        const ull* wp = (const ull*)&Wh[kk * 16];
        ull w0v = wp[0], w1v = wp[1], w2v = wp[2], w3v = wp[3];
        ull x0 = dup2(xq.x), x1 = dup2(xq.y), x2 = dup2(xq.z), x3 = dup2(xq.w);
        fma2(acc[0][0], x0, w0v); fma2(acc[1][0], x0, w1v);
        fma2(acc[2][0], x0, w2v); fma2(acc[3][0], x0, w3v);
        fma2(acc[0][1], x1, w0v); fma2(acc[1][1], x1, w1v);
        fma2(acc[2][1], x1, w2v); fma2(acc[3][1], x1, w3v);
        fma2(acc[0][2], x2, w0v); fma2(acc[1][2], x2, w1v);
        fma2(acc[2][2], x2, w2v); fma2(acc[3][2], x2, w3v);
        fma2(acc[0][3], x3, w0v); fma2(acc[1][3], x3, w1v);
        fma2(acc[2][3], x3, w2v); fma2(acc[3][3], x3, w3v);
    }

    // combine k-halves: kh==1 dumps accs into (dead) patch smem, kh==0 adds.
    __syncthreads();
    ull* red = (ull*)P2;                 // [16][64] (pq-major, thread fast)
    if (kh == 1) {
#pragma unroll
        for (int p = 0; p < 4; p++)
#pragma unroll
            for (int q = 0; q < 4; q++)
                red[(p * 4 + q) * 64 + (t - 64)] = acc[p][q];
    }
    __syncthreads();

    if (kh == 0) {
#pragma unroll
        for (int p = 0; p < 4; p++)
#pragma unroll
            for (int q = 0; q < 4; q++)
                add2(acc[p][q], red[(p * 4 + q) * 64 + t]);

        float bias[8];
#pragma unroll
        for (int r = 0; r < 8; r++) bias[r] = b0[((half * 8 + r) * 55 + i) * 55 + j];

#pragma unroll
        for (int q = 0; q < 4; q++) {
            int b = bg * 4 + q;
            float s = 0.f, ss = 0.f;
#pragma unroll
            for (int p = 0; p < 4; p++) {
                float lo, hi; unpk(acc[p][q], lo, hi);
                int oc0 = half * 8 + 2 * p, oc1 = oc0 + 1;
                float v0 = fmaxf(lo + bias[2 * p], 0.f);
                float v1 = fmaxf(hi + bias[2 * p + 1], 0.f);
                g_y0[((i * 4 + (oc0 >> 2)) * 220 + (j * 4 + (oc0 & 3))) * 128 + b] = v0;
                g_y0[((i * 4 + (oc1 >> 2)) * 220 + (j * 4 + (oc1 & 3))) * 128 + b] = v1;
                s += v0 + v1;
                ss = fmaf(v0, v0, ss);
                ss = fmaf(v1, v1, ss);
            }
            Ssum[half * 128 + b] = s;
            Sss[half * 128 + b]  = ss;
        }
    }
    __syncthreads();
    if (t < 32) {
        int blk = blockIdx.y * 55 + blockIdx.x;
        for (int b = t; b < 128; b += 32) {
            g_p0s[blk * 128 + b]  = Ssum[b] + Ssum[128 + b];
            g_p0ss[blk * 128 + b] = Sss[b] + Sss[128 + b];
        }
    }
}

// ---------------------------------------------------------------------------
// reduce per-block LN partials -> mean, rstd. grid 128 (one block per image)
// ---------------------------------------------------------------------------
__global__ void ln2_kernel(int which) {
    const float* ps  = which ? g_p1s  : g_p0s;
    const float* pss = which ? g_p1ss : g_p0ss;
    float* gm        = which ? g_m1 : g_m0;
    float* gr        = which ? g_r1 : g_r0;
    const int nblk   = which ? 2809 : 3025;
    const float invn = which ? (1.f / 25281.f) : (1.f / 48400.f);
    int b = blockIdx.x, t = threadIdx.x;
    float s = 0.f, ss = 0.f;
    for (int k = t; k < nblk; k += 256) {
        s  += ps[k * 128 + b];
        ss += pss[k * 128 + b];
    }
    __shared__ float r1[8], r2[8];
    for (int o = 16; o; o >>= 1) {
        s  += __shfl_xor_sync(0xffffffffu, s, o);
        ss += __shfl_xor_sync(0xffffffffu, ss, o);
    }
    if ((t & 31) == 0) { r1[t >> 5] = s; r2[t >> 5] = ss; }
    __syncthreads();
    if (t == 0) {
        s = 0.f; ss = 0.f;
        for (int w = 0; w < 8; w++) { s += r1[w]; ss += r2[w]; }
        float m = s * invn;
        float var = ss * invn - m * m;
        gm[b] = m;
        gr[b] = rsqrtf(var + 1e-5f);
    }
}

// ---------------------------------------------------------------------------
// normalize (layer0) + 2x2 maxpool -> g_h1 [pos][b]  (all coalesced)
// ---------------------------------------------------------------------------
__global__ void norm_pool_kernel(const float* __restrict__ g0,
                                 const float* __restrict__ be0) {
    int idx = blockIdx.x * 256 + threadIdx.x;
    if (idx >= BSZ * 110 * 110) return;
    int b = idx & 127, pos = idx >> 7;
    int r = pos / 110, c = pos - r * 110;
    float m = g_m0[b], rs = g_r0[b];
    float mx = -3.4e38f;
#pragma unroll
    for (int dr = 0; dr < 2; dr++)
#pragma unroll
        for (int dc = 0; dc < 2; dc++) {
            int P = (2 * r + dr) * 220 + 2 * c + dc;
            float v = (g_y0[P * 128 + b] - m) * rs * g0[P] + be0[P];
            mx = fmaxf(mx, v);
        }
    g_h1[pos * 128 + b] = mx;
}

// ---------------------------------------------------------------------------
// conv1: local conv 1x6x6 stride 2, 9 oc (packed), + bias + relu, HWB scatter,
// fused LN partials. grid (53,53), 128 threads (1 batch each).  [R3 proven]
// ---------------------------------------------------------------------------
__global__ void conv1_kernel(const float* __restrict__ w1,
                             const float* __restrict__ b1) {
    __shared__ float Ws2[36 * 10];       // [k][oc] padded to 10 (8B-aligned pairs)
    __shared__ float P2[36 * 128];       // [k][b]
    int i = blockIdx.x, j = blockIdx.y, t = threadIdx.x;
    const float* wloc = w1 + (i * 53 + j) * 324;
    for (int e = t; e < 324; e += 128) {
        int oc = e / 36, k = e - oc * 36;
        Ws2[k * 10 + oc] = wloc[e];
    }
    for (int e = t; e < 36 * 128; e += 128) {
        int b = e & 127, kk = e >> 7;
        int di = kk / 6, dj = kk - di * 6;
        P2[kk * 128 + b] = g_h1[((2 * i + di) * 110 + 2 * j + dj) * 128 + b];
    }
    __syncthreads();

    ull a[4] = {0ull, 0ull, 0ull, 0ull};
    float a8 = 0.f;
#pragma unroll 4
    for (int k = 0; k < 36; k++) {
        float xv = P2[k * 128 + t];
        ull xd = dup2(xv);
        const ull* wp = (const ull*)&Ws2[k * 10];
        fma2(a[0], xd, wp[0]);
        fma2(a[1], xd, wp[1]);
        fma2(a[2], xd, wp[2]);
        fma2(a[3], xd, wp[3]);
        a8 = fmaf(xv, Ws2[k * 10 + 8], a8);
    }
    float v[9];
    unpk(a[0], v[0], v[1]); unpk(a[1], v[2], v[3]);
    unpk(a[2], v[4], v[5]); unpk(a[3], v[6], v[7]);
    v[8] = a8;
    float s = 0.f, ss = 0.f;
#pragma unroll
    for (int oc = 0; oc < 9; oc++) {
        float val = fmaxf(v[oc] + b1[(oc * 53 + i) * 53 + j], 0.f);
        int row = i * 3 + oc / 3, col = j * 3 + oc % 3;
        g_y1[(row * 159 + col) * 128 + t] = val;
        s += val;
        ss = fmaf(val, val, ss);
    }
    int blk = blockIdx.y * 53 + blockIdx.x;
    g_p1s[blk * 128 + t]  = s;
    g_p1ss[blk * 128 + t] = ss;
}

// ---------------------------------------------------------------------------
// normalize layer1 -> g_feat [k][b]
// ---------------------------------------------------------------------------
__global__ void norm1_kernel(const float* __restrict__ g1,
                             const float* __restrict__ be1) {
    int idx = blockIdx.x * 256 + threadIdx.x;
    if (idx >= BSZ * FCK) return;
    int b = idx & 127, k = idx >> 7;
    float m = g_m1[b], rs = g_r1[b];
    g_feat[k * 128 + b] = (g_y1[k * 128 + b] - m) * rs * g1[k] + be1[k];
}

// ---------------------------------------------------------------------------
// FC: logits_part[sk][b][n] = sum_{k in chunk} feat[k][b] * fcw[n][k]
// grid (8, SK), 256 threads; Btile=128, Ntile=128, KT=32; 8b x 8n per thread
// [R4-proven form]
// ---------------------------------------------------------------------------
__global__ void fc_kernel(const float* __restrict__ fcw) {
    __shared__ float Fs[32 * 128];
    __shared__ float Wsm[32 * 128];
    int t = threadIdx.x;
    int nblk = blockIdx.x, sk = blockIdx.y;
    int kbeg = (int)((long long)FCK * sk / SK);
    int kend = (int)((long long)FCK * (sk + 1) / SK);
    int tb = t & 15, tn = t >> 4;
    int nbase = nblk * 128;

    ull acc[8][4];
#pragma unroll
    for (int r = 0; r < 8; r++)
#pragma unroll
        for (int q = 0; q < 4; q++) acc[r][q] = 0ull;

    for (int k0 = kbeg; k0 < kend; k0 += 32) {
        // F tile: feat is [k][b] -> lanes vary b (coalesced)
#pragma unroll
        for (int e0 = 0; e0 < 4096; e0 += 256) {
            int e = e0 + t;
            int b = e & 127, kt = e >> 7;
            int k = k0 + kt;
            float fv = (k < kend) ? g_feat[k * 128 + b] : 0.f;
            int sw = (kt << 7) + ((((b >> 2) ^ kt) & 31) << 2) + (b & 3);
            Fs[sw] = fv;
        }
        // W tile: fcw is [n][k] -> lanes vary k (coalesced)
#pragma unroll
        for (int e0 = 0; e0 < 4096; e0 += 256) {
            int e = e0 + t;
            int kt = e & 31, row = e >> 5;
            int k = k0 + kt;
            float wv = 0.f;
            int ng = nbase + row;
            if (k < kend && ng < 1000) wv = fcw[ng * FCK + k];
            int sw = (kt << 7) + ((((row >> 2) ^ kt) & 31) << 2) + (row & 3);
            Wsm[sw] = wv;
        }
        __syncthreads();
#pragma unroll 2
        for (int kt = 0; kt < 32; kt++) {
            int base = kt << 7;
            ulonglong2 fA = *(const ulonglong2*)&Fs[base + ((((2 * tb)     ^ kt) & 31) << 2)];
            ulonglong2 fB = *(const ulonglong2*)&Fs[base + ((((2 * tb + 1) ^ kt) & 31) << 2)];
            float4 wA = *(const float4*)&Wsm[base + ((((2 * tn)     ^ kt) & 31) << 2)];
            float4 wB = *(const float4*)&Wsm[base + ((((2 * tn + 1) ^ kt) & 31) << 2)];
            ull wd[8] = {dup2(wA.x), dup2(wA.y), dup2(wA.z), dup2(wA.w),
                         dup2(wB.x), dup2(wB.y), dup2(wB.z), dup2(wB.w)};
#pragma unroll
            for (int r = 0; r < 8; r++) {
                fma2(acc[r][0], fA.x, wd[r]);
                fma2(acc[r][1], fA.y, wd[r]);
                fma2(acc[r][2], fB.x, wd[r]);
                fma2(acc[r][3], fB.y, wd[r]);
            }
        }
        __syncthreads();
    }

    int b0 = tb * 8;
    float* outp = g_part + sk * (BSZ * 1000);
#pragma unroll
    for (int r = 0; r < 8; r++) {
        int n = nbase + tn * 8 + r;
        if (n >= 1000) continue;
#pragma unroll
        for (int q = 0; q < 4; q++) {
            float lo, hi;
            unpk(acc[r][q], lo, hi);
            outp[(b0 + 2 * q) * 1000 + n] = lo;
            outp[(b0 + 2 * q + 1) * 1000 + n] = hi;
        }
    }
}

// ---------------------------------------------------------------------------
// reduce split-K partials (fixed order -> deterministic) + bias + softmax
// logits kept in smem (no global roundtrip)
// ---------------------------------------------------------------------------
__global__ void softmax_kernel(const float* __restrict__ fcb,
                               float* __restrict__ out) {
    int b = blockIdx.x, t = threadIdx.x;
    __shared__ float lg[1000];
    __shared__ float red[8];
    __shared__ float bc;

    for (int n = t; n < 1000; n += 256) {
        float v = fcb[n];
        for (int s = 0; s < SK; s++) v += g_part[(s * BSZ + b) * 1000 + n];
        lg[n] = v;
    }
    __syncthreads();

    float mx = -3.4e38f;
    for (int n = t; n < 1000; n += 256) mx = fmaxf(mx, lg[n]);
    for (int o = 16; o; o >>= 1) mx = fmaxf(mx, __shfl_xor_sync(0xffffffffu, mx, o));
    if ((t & 31) == 0) red[t >> 5] = mx;
    __syncthreads();
    if (t == 0) {
        float m = red[0];
        for (int w = 1; w < 8; w++) m = fmaxf(m, red[w]);
        bc = m;
    }
    __syncthreads();
    mx = bc;

    float s = 0.f;
    for (int n = t; n < 1000; n += 256) s += expf(lg[n] - mx);
    for (int o = 16; o; o >>= 1) s += __shfl_xor_sync(0xffffffffu, s, o);
    __syncthreads();
    if ((t & 31) == 0) red[t >> 5] = s;
    __syncthreads();
    if (t == 0) {
        float tot = 0.f;
        for (int w = 0; w < 8; w++) tot += red[w];
        bc = 1.f / tot;
    }
    __syncthreads();
    float inv = bc;
    for (int n = t; n < 1000; n += 256)
        out[b * 1000 + n] = expf(lg[n] - mx) * inv;
}

// ---------------------------------------------------------------------------

extern "C" void kernel_launch(void* const* d_in, const int* in_sizes, int n_in,
                              void* d_out, int out_size) {
    const float* x   = (const float*)d_in[0];
    const float* w0  = (const float*)d_in[1];
    const float* b0  = (const float*)d_in[2];
    const float* g0  = (const float*)d_in[3];
    const float* be0 = (const float*)d_in[4];
    const float* w1  = (const float*)d_in[5];
    const float* b1  = (const float*)d_in[6];
    const float* g1  = (const float*)d_in[7];
    const float* be1 = (const float*)d_in[8];
    const float* fcw = (const float*)d_in[9];
    const float* fcb = (const float*)d_in[10];
    float* out = (float*)d_out;

    const int smem0 = (3072 + 192 * 128 + 512) * (int)sizeof(float);  // 112640 B
    cudaFuncSetAttribute(conv0_kernel, cudaFuncAttributeMaxDynamicSharedMemorySize, smem0);

    conv0_kernel<<<dim3(55, 55), 128, smem0>>>(x, w0, b0);
    ln2_kernel<<<128, 256>>>(0);
    norm_pool_kernel<<<(BSZ * 110 * 110 + 255) / 256, 256>>>(g0, be0);
    conv1_kernel<<<dim3(53, 53), 128>>>(w1, b1);
    ln2_kernel<<<128, 256>>>(1);
    norm1_kernel<<<(BSZ * FCK + 255) / 256, 256>>>(g1, be1);
    fc_kernel<<<dim3(8, SK), 256>>>(fcw);
    softmax_kernel<<<128, 256>>>(fcb, out);
}

// round 8
// speedup vs baseline: 1.2547x; 1.0968x over previous
#include <cuda_runtime.h>
#include <cuda_bf16.h>
#include <cstdint>

typedef unsigned long long ull;

__device__ __forceinline__ ull dup2(float x) {
    ull r; asm("mov.b64 %0, {%1, %1};" : "=l"(r) : "f"(x)); return r;
}
__device__ __forceinline__ void fma2(ull& d, ull a, ull b) {
    asm("fma.rn.f32x2 %0, %1, %2, %0;" : "+l"(d) : "l"(a), "l"(b));
}
__device__ __forceinline__ void add2(ull& d, ull a) {
    asm("add.rn.f32x2 %0, %0, %1;" : "+l"(d) : "l"(a));
}
__device__ __forceinline__ void unpk(ull v, float& lo, float& hi) {
    asm("mov.b64 {%0, %1}, %2;" : "=f"(lo), "=f"(hi) : "l"(v));
}
__device__ __forceinline__ uint32_t smem_u32(const void* p) {
    uint32_t a;
    asm("{ .reg .u64 tmp; cvta.to.shared.u64 tmp, %1; cvt.u32.u64 %0, tmp; }"
        : "=r"(a) : "l"(p));
    return a;
}
// pack two floats to bf16x2 (lo bits = a, hi bits = b)
__device__ __forceinline__ uint32_t pack_bf16x2(float a, float b) {
    uint32_t r;
    asm("cvt.rn.bf16x2.f32 %0, %1, %2;" : "=r"(r) : "f"(b), "f"(a));
    return r;
}
#define LDSM_X4(r, addr) \
    asm volatile("ldmatrix.sync.aligned.m8n8.x4.shared.b16 {%0,%1,%2,%3}, [%4];" \
                 : "=r"((r)[0]), "=r"((r)[1]), "=r"((r)[2]), "=r"((r)[3]) : "r"(addr))
#define MMA_BF16(c, a, b0v, b1v) \
    asm volatile("mma.sync.aligned.m16n8k16.row.col.f32.bf16.bf16.f32 " \
                 "{%0,%1,%2,%3}, {%4,%5,%6,%7}, {%8,%9}, {%0,%1,%2,%3};" \
                 : "+f"((c)[0]), "+f"((c)[1]), "+f"((c)[2]), "+f"((c)[3]) \
                 : "r"((a)[0]), "r"((a)[1]), "r"((a)[2]), "r"((a)[3]), \
                   "r"(b0v), "r"(b1v))

#define BSZ 128
#define FCK 25281
#define KPAD 25344      // 18 * 22 * 64
#define SK2 18
#define NCHUNK 22
#define FPITCH 72       // smem row pitch in bf16 (144 B = 9*16: aligned + conflict-free)

// scratch (no allocs allowed -> __device__ globals)
__device__ float g_y0[220 * 220 * BSZ];
__device__ float g_p0s[3025 * BSZ];
__device__ float g_p0ss[3025 * BSZ];
__device__ float g_m0[BSZ], g_r0[BSZ];
__device__ float g_h1[110 * 110 * BSZ];
__device__ float g_y1[159 * 159 * BSZ];
__device__ float g_p1s[2809 * BSZ];
__device__ float g_p1ss[2809 * BSZ];
__device__ float g_m1[BSZ], g_r1[BSZ];
__device__ uint4 g_fT_hi[(size_t)BSZ * KPAD / 8];  // feat hi bf16, [b][k]
__device__ uint4 g_fT_lo[(size_t)BSZ * KPAD / 8];  // feat lo bf16, [b][k]
__device__ float g_part[SK2 * BSZ * 1000];

// ---------------------------------------------------------------------------
// conv0 [R4-proven]: local conv 3x8x8 s4, 16oc, bias+relu, HWB, LN partials
// ---------------------------------------------------------------------------
__global__ void __launch_bounds__(128) conv0_kernel(const float* __restrict__ x,
                                                    const float* __restrict__ w0,
                                                    const float* __restrict__ b0) {
    extern __shared__ float sm[];
    float* Ws   = sm;
    float* P2   = sm + 3072;
    float* Ssum = sm + 3072 + 192 * 128;
    float* Sss  = Ssum + 256;
    const int i = blockIdx.x, j = blockIdx.y;
    const int t = threadIdx.x;

    const float* wloc = w0 + (i * 55 + j) * 3072;
    for (int e = t; e < 3072; e += 128) {
        int oc = e / 192, k = e - oc * 192;
        Ws[k * 16 + oc] = wloc[e];
    }
    for (int e = t; e < 6144; e += 128) {
        int b = e & 127, kq = e >> 7;
        int c = kq >> 4, di = (kq >> 1) & 7, djq = kq & 1;
        float4 v = *(const float4*)&x[((b * 3 + c) * 224 + (i * 4 + di)) * 224
                                      + j * 4 + djq * 4];
        int k = kq * 4;
        P2[(k + 0) * 128 + b] = v.x;
        P2[(k + 1) * 128 + b] = v.y;
        P2[(k + 2) * 128 + b] = v.z;
        P2[(k + 3) * 128 + b] = v.w;
    }
    __syncthreads();

    const int bg = t & 31;
    const int half = (t >> 5) & 1;
    const int kh = t >> 6;
    const float* Wh = Ws + half * 8;
    ull acc[4][4];
#pragma unroll
    for (int p = 0; p < 4; p++)
#pragma unroll
        for (int q = 0; q < 4; q++) acc[p][q] = 0ull;

    const int kbase = kh * 96;
#pragma unroll 4
    for (int k = 0; k < 96; k++) {
        int kk = kbase + k;
        float4 xq = *(const float4*)&P2[kk * 128 + bg * 4];
        const ull* wp = (const ull*)&Wh[kk * 16];
        ull w0v = wp[0], w1v = wp[1], w2v = wp[2], w3v = wp[3];
        ull x0 = dup2(xq.x), x1 = dup2(xq.y), x2 = dup2(xq.z), x3 = dup2(xq.w);
        fma2(acc[0][0], x0, w0v); fma2(acc[1][0], x0, w1v);
        fma2(acc[2][0], x0, w2v); fma2(acc[3][0], x0, w3v);
        fma2(acc[0][1], x1, w0v); fma2(acc[1][1], x1, w1v);
        fma2(acc[2][1], x1, w2v); fma2(acc[3][1], x1, w3v);
        fma2(acc[0][2], x2, w0v); fma2(acc[1][2], x2, w1v);
        fma2(acc[2][2], x2, w2v); fma2(acc[3][2], x2, w3v);
        fma2(acc[0][3], x3, w0v); fma2(acc[1][3], x3, w1v);
        fma2(acc[2][3], x3, w2v); fma2(acc[3][3], x3, w3v);
    }

    __syncthreads();
    ull* red = (ull*)P2;
    if (kh == 1) {
#pragma unroll
        for (int p = 0; p < 4; p++)
#pragma unroll
            for (int q = 0; q < 4; q++)
                red[(p * 4 + q) * 64 + (t - 64)] = acc[p][q];
    }
    __syncthreads();

    if (kh == 0) {
#pragma unroll
        for (int p = 0; p < 4; p++)
#pragma unroll
            for (int q = 0; q < 4; q++)
                add2(acc[p][q], red[(p * 4 + q) * 64 + t]);

        float bias[8];
#pragma unroll
        for (int r = 0; r < 8; r++) bias[r] = b0[((half * 8 + r) * 55 + i) * 55 + j];

#pragma unroll
        for (int q = 0; q < 4; q++) {
            int b = bg * 4 + q;
            float s = 0.f, ss = 0.f;
#pragma unroll
            for (int p = 0; p < 4; p++) {
                float lo, hi; unpk(acc[p][q], lo, hi);
                int oc0 = half * 8 + 2 * p, oc1 = oc0 + 1;
                float v0 = fmaxf(lo + bias[2 * p], 0.f);
                float v1 = fmaxf(hi + bias[2 * p + 1], 0.f);
                g_y0[((i * 4 + (oc0 >> 2)) * 220 + (j * 4 + (oc0 & 3))) * 128 + b] = v0;
                g_y0[((i * 4 + (oc1 >> 2)) * 220 + (j * 4 + (oc1 & 3))) * 128 + b] = v1;
                s += v0 + v1;
                ss = fmaf(v0, v0, ss);
                ss = fmaf(v1, v1, ss);
            }
            Ssum[half * 128 + b] = s;
            Sss[half * 128 + b]  = ss;
        }
    }
    __syncthreads();
    if (t < 32) {
        int blk = blockIdx.y * 55 + blockIdx.x;
        for (int b = t; b < 128; b += 32) {
            g_p0s[blk * 128 + b]  = Ssum[b] + Ssum[128 + b];
            g_p0ss[blk * 128 + b] = Sss[b] + Sss[128 + b];
        }
    }
}

// ---------------------------------------------------------------------------
// reduce LN partials -> mean, rstd
// ---------------------------------------------------------------------------
__global__ void ln2_kernel(int which) {
    const float* ps  = which ? g_p1s  : g_p0s;
    const float* pss = which ? g_p1ss : g_p0ss;
    float* gm        = which ? g_m1 : g_m0;
    float* gr        = which ? g_r1 : g_r0;
    const int nblk   = which ? 2809 : 3025;
    const float invn = which ? (1.f / 25281.f) : (1.f / 48400.f);
    int b = blockIdx.x, t = threadIdx.x;
    float s = 0.f, ss = 0.f;
    for (int k = t; k < nblk; k += 256) {
        s  += ps[k * 128 + b];
        ss += pss[k * 128 + b];
    }
    __shared__ float r1[8], r2[8];
    for (int o = 16; o; o >>= 1) {
        s  += __shfl_xor_sync(0xffffffffu, s, o);
        ss += __shfl_xor_sync(0xffffffffu, ss, o);
    }
    if ((t & 31) == 0) { r1[t >> 5] = s; r2[t >> 5] = ss; }
    __syncthreads();
    if (t == 0) {
        s = 0.f; ss = 0.f;
        for (int w = 0; w < 8; w++) { s += r1[w]; ss += r2[w]; }
        float m = s * invn;
        float var = ss * invn - m * m;
        gm[b] = m;
        gr[b] = rsqrtf(var + 1e-5f);
    }
}

// ---------------------------------------------------------------------------
// normalize (layer0) + 2x2 maxpool -> g_h1 [pos][b]
// ---------------------------------------------------------------------------
__global__ void norm_pool_kernel(const float* __restrict__ g0,
                                 const float* __restrict__ be0) {
    int idx = blockIdx.x * 256 + threadIdx.x;
    if (idx >= BSZ * 110 * 110) return;
    int b = idx & 127, pos = idx >> 7;
    int r = pos / 110, c = pos - r * 110;
    float m = g_m0[b], rs = g_r0[b];
    float mx = -3.4e38f;
#pragma unroll
    for (int dr = 0; dr < 2; dr++)
#pragma unroll
        for (int dc = 0; dc < 2; dc++) {
            int P = (2 * r + dr) * 220 + 2 * c + dc;
            float v = (g_y0[P * 128 + b] - m) * rs * g0[P] + be0[P];
            mx = fmaxf(mx, v);
        }
    g_h1[pos * 128 + b] = mx;
}

// ---------------------------------------------------------------------------
// conv1 [R3-proven]: local conv 1x6x6 s2, 9oc, bias+relu, HWB, LN partials
// ---------------------------------------------------------------------------
__global__ void conv1_kernel(const float* __restrict__ w1,
                             const float* __restrict__ b1) {
    __shared__ float Ws2[36 * 10];
    __shared__ float P2[36 * 128];
    int i = blockIdx.x, j = blockIdx.y, t = threadIdx.x;
    const float* wloc = w1 + (i * 53 + j) * 324;
    for (int e = t; e < 324; e += 128) {
        int oc = e / 36, k = e - oc * 36;
        Ws2[k * 10 + oc] = wloc[e];
    }
    for (int e = t; e < 36 * 128; e += 128) {
        int b = e & 127, kk = e >> 7;
        int di = kk / 6, dj = kk - di * 6;
        P2[kk * 128 + b] = g_h1[((2 * i + di) * 110 + 2 * j + dj) * 128 + b];
    }
    __syncthreads();

    ull a[4] = {0ull, 0ull, 0ull, 0ull};
    float a8 = 0.f;
#pragma unroll 4
    for (int k = 0; k < 36; k++) {
        float xv = P2[k * 128 + t];
        ull xd = dup2(xv);
        const ull* wp = (const ull*)&Ws2[k * 10];
        fma2(a[0], xd, wp[0]);
        fma2(a[1], xd, wp[1]);
        fma2(a[2], xd, wp[2]);
        fma2(a[3], xd, wp[3]);
        a8 = fmaf(xv, Ws2[k * 10 + 8], a8);
    }
    float v[9];
    unpk(a[0], v[0], v[1]); unpk(a[1], v[2], v[3]);
    unpk(a[2], v[4], v[5]); unpk(a[3], v[6], v[7]);
    v[8] = a8;
    float s = 0.f, ss = 0.f;
#pragma unroll
    for (int oc = 0; oc < 9; oc++) {
        float val = fmaxf(v[oc] + b1[(oc * 53 + i) * 53 + j], 0.f);
        int row = i * 3 + oc / 3, col = j * 3 + oc % 3;
        g_y1[(row * 159 + col) * 128 + t] = val;
        s += val;
        ss = fmaf(val, val, ss);
    }
    int blk = blockIdx.y * 53 + blockIdx.x;
    g_p1s[blk * 128 + t]  = s;
    g_p1ss[blk * 128 + t] = ss;
}

// ---------------------------------------------------------------------------
// norm1t: normalize layer1 + transpose to [b][k] + bf16 hi/lo split.
// grid 396 (64-k tiles), 256 threads.
// ---------------------------------------------------------------------------
__global__ void __launch_bounds__(256) norm1t_kernel(const float* __restrict__ g1,
                                                     const float* __restrict__ be1) {
    __shared__ float Tb[64][129];
    const int k0 = blockIdx.x * 64;
    const int t = threadIdx.x;
#pragma unroll
    for (int p = 0; p < 8; p++) {
        int e = p * 256 + t;
        int kl = e >> 5, bq = e & 31;
        int k = k0 + kl;
        float4 v = make_float4(0.f, 0.f, 0.f, 0.f);
        if (k < FCK) {
            float4 y = *(const float4*)&g_y1[k * 128 + bq * 4];
            float4 m = *(const float4*)&g_m1[bq * 4];
            float4 r = *(const float4*)&g_r1[bq * 4];
            float gk = g1[k], bk = be1[k];
            v.x = fmaf((y.x - m.x) * r.x, gk, bk);
            v.y = fmaf((y.y - m.y) * r.y, gk, bk);
            v.z = fmaf((y.z - m.z) * r.z, gk, bk);
            v.w = fmaf((y.w - m.w) * r.w, gk, bk);
        }
        Tb[kl][bq * 4 + 0] = v.x;
        Tb[kl][bq * 4 + 1] = v.y;
        Tb[kl][bq * 4 + 2] = v.z;
        Tb[kl][bq * 4 + 3] = v.w;
    }
    __syncthreads();

    const int b = t >> 1, half = t & 1;
    uint32_t oh[16], ol[16];
#pragma unroll
    for (int u = 0; u < 16; u++) {
        float v0 = Tb[half * 32 + 2 * u][b];
        float v1 = Tb[half * 32 + 2 * u + 1][b];
        uint32_t ph = pack_bf16x2(v0, v1);           // lo=v0, hi=v1
        float h0 = __uint_as_float(ph << 16);
        float h1 = __uint_as_float(ph & 0xFFFF0000u);
        oh[u] = ph;
        ol[u] = pack_bf16x2(v0 - h0, v1 - h1);
    }
    uint32_t* dh = (uint32_t*)g_fT_hi + (size_t)b * (KPAD / 2) + (k0 + half * 32) / 2;
    uint32_t* dl = (uint32_t*)g_fT_lo + (size_t)b * (KPAD / 2) + (k0 + half * 32) / 2;
#pragma unroll
    for (int q = 0; q < 4; q++) {
        ((uint4*)dh)[q] = make_uint4(oh[4 * q], oh[4 * q + 1], oh[4 * q + 2], oh[4 * q + 3]);
        ((uint4*)dl)[q] = make_uint4(ol[4 * q], ol[4 * q + 1], ol[4 * q + 2], ol[4 * q + 3]);
    }
}

// ---------------------------------------------------------------------------
// fc_mma: bf16 hi/lo-split GEMM on mma.sync (HMMA).
// logits_part[sk][b][n] = sum_k fcw[n][k] * feat[b][k]
// grid (8, 18), 256 threads (8 warps); warp w owns n-rows [w*16, w*16+16).
// Per 64-k tile: stage fcw hi/lo + feat hi/lo in smem (pitch-72 bf16),
// ldmatrix.x4 fragments, 3 MMAs per (k16, 8b) tile (drop lo*lo).
// ---------------------------------------------------------------------------
__global__ void __launch_bounds__(256) fc_mma_kernel(const float* __restrict__ fcw) {
    extern __shared__ __align__(16) __nv_bfloat16 sb[];
    __nv_bfloat16* Wh = sb;                  // [128][72]
    __nv_bfloat16* Wl = Wh + 128 * FPITCH;
    __nv_bfloat16* Fh = Wl + 128 * FPITCH;
    __nv_bfloat16* Fl = Fh + 128 * FPITCH;
    const uint32_t base = smem_u32(sb);
    const uint32_t WH_OFF = 0, WL_OFF = 128 * FPITCH * 2,
                   FH_OFF = 2 * 128 * FPITCH * 2, FL_OFF = 3 * 128 * FPITCH * 2;

    const int t = threadIdx.x, wid = t >> 5, lane = t & 31;
    const int g = lane >> 2, tg = lane & 3;
    const int tq = lane >> 3, tr = lane & 7;
    const int nbase = blockIdx.x * 128;
    const int sk = blockIdx.y;

    float acc[16][4];
#pragma unroll
    for (int bt = 0; bt < 16; bt++)
#pragma unroll
        for (int q = 0; q < 4; q++) acc[bt][q] = 0.f;

    // ldmatrix row addresses (byte offsets within each matrix region)
    const uint32_t aRow = wid * 16 + (tq & 1) * 8 + tr;      // A: n-row
    const uint32_t aKof = (tq >> 1) * 8;                     // A: +8 k for mats 2,3
    const uint32_t bRowB = (tq & 2) * 4 + tr;                // B: b-row within 16
    const uint32_t bKof = (tq & 1) * 8;                      // B: +8 k for mats 1,3

    for (int it = 0; it < NCHUNK; it++) {
        const int k0 = (sk * NCHUNK + it) * 64;
        __syncthreads();
        // stage fcw -> bf16 hi/lo (32 scalars per thread)
#pragma unroll 4
        for (int p = 0; p < 32; p++) {
            int e = p * 256 + t;
            int row = e >> 6, c = e & 63;
            int ng = nbase + row, k = k0 + c;
            float v = (ng < 1000 && k < FCK) ? __ldg(&fcw[ng * FCK + k]) : 0.f;
            __nv_bfloat16 h = __float2bfloat16(v);
            __nv_bfloat16 l = __float2bfloat16(v - __bfloat162float(h));
            Wh[row * FPITCH + c] = h;
            Wl[row * FPITCH + c] = l;
        }
        // stage feat hi/lo (uint4 chunks, aligned: 144B pitch is 16B-multiple)
#pragma unroll
        for (int p = 0; p < 4; p++) {
            int e = p * 256 + t;
            int b = e >> 3, q = e & 7;
            size_t idx = ((size_t)b * KPAD + k0) / 8 + q;
            *(uint4*)&Fh[b * FPITCH + q * 8] = g_fT_hi[idx];
            *(uint4*)&Fl[b * FPITCH + q * 8] = g_fT_lo[idx];
        }
        __syncthreads();

#pragma unroll
        for (int k16 = 0; k16 < 4; k16++) {
            uint32_t ak = (k16 * 16 + aKof) * 2;
            uint32_t ah[4], al[4];
            LDSM_X4(ah, base + WH_OFF + aRow * (FPITCH * 2) + ak);
            LDSM_X4(al, base + WL_OFF + aRow * (FPITCH * 2) + ak);
            uint32_t bk = (k16 * 16 + bKof) * 2;
#pragma unroll
            for (int bt2 = 0; bt2 < 8; bt2++) {
                uint32_t brow = bt2 * 16 + bRowB;
                uint32_t bh[4], bl[4];
                LDSM_X4(bh, base + FH_OFF + brow * (FPITCH * 2) + bk);
                LDSM_X4(bl, base + FL_OFF + brow * (FPITCH * 2) + bk);
                MMA_BF16(acc[2 * bt2],     ah, bh[0], bh[1]);
                MMA_BF16(acc[2 * bt2 + 1], ah, bh[2], bh[3]);
                MMA_BF16(acc[2 * bt2],     ah, bl[0], bl[1]);
                MMA_BF16(acc[2 * bt2 + 1], ah, bl[2], bl[3]);
                MMA_BF16(acc[2 * bt2],     al, bh[0], bh[1]);
                MMA_BF16(acc[2 * bt2 + 1], al, bh[2], bh[3]);
            }
        }
    }

    // epilogue: D frag (m16n8): c0,c1 -> row g, cols tg*2,+1; c2,c3 -> row g+8
    float* outp = g_part + sk * (BSZ * 1000);
    const int n0 = nbase + wid * 16 + g;
    const int n1 = n0 + 8;
#pragma unroll
    for (int bt = 0; bt < 16; bt++) {
        int b0 = bt * 8 + tg * 2;
        if (n0 < 1000) {
            outp[b0 * 1000 + n0]       = acc[bt][0];
            outp[(b0 + 1) * 1000 + n0] = acc[bt][1];
        }
        if (n1 < 1000) {
            outp[b0 * 1000 + n1]       = acc[bt][2];
            outp[(b0 + 1) * 1000 + n1] = acc[bt][3];
        }
    }
}

// ---------------------------------------------------------------------------
// reduce split-K partials (fixed order -> deterministic) + bias + softmax
// ---------------------------------------------------------------------------
__global__ void softmax_kernel(const float* __restrict__ fcb,
                               float* __restrict__ out) {
    int b = blockIdx.x, t = threadIdx.x;
    __shared__ float lg[1000];
    __shared__ float red[8];
    __shared__ float bc;

    for (int n = t; n < 1000; n += 256) {
        float v = fcb[n];
        for (int s = 0; s < SK2; s++) v += g_part[(s * BSZ + b) * 1000 + n];
        lg[n] = v;
    }
    __syncthreads();

    float mx = -3.4e38f;
    for (int n = t; n < 1000; n += 256) mx = fmaxf(mx, lg[n]);
    for (int o = 16; o; o >>= 1) mx = fmaxf(mx, __shfl_xor_sync(0xffffffffu, mx, o));
    if ((t & 31) == 0) red[t >> 5] = mx;
    __syncthreads();
    if (t == 0) {
        float m = red[0];
        for (int w = 1; w < 8; w++) m = fmaxf(m, red[w]);
        bc = m;
    }
    __syncthreads();
    mx = bc;

    float s = 0.f;
    for (int n = t; n < 1000; n += 256) s += expf(lg[n] - mx);
    for (int o = 16; o; o >>= 1) s += __shfl_xor_sync(0xffffffffu, s, o);
    __syncthreads();
    if ((t & 31) == 0) red[t >> 5] = s;
    __syncthreads();
    if (t == 0) {
        float tot = 0.f;
        for (int w = 0; w < 8; w++) tot += red[w];
        bc = 1.f / tot;
    }
    __syncthreads();
    float inv = bc;
    for (int n = t; n < 1000; n += 256)
        out[b * 1000 + n] = expf(lg[n] - mx) * inv;
}

// ---------------------------------------------------------------------------

extern "C" void kernel_launch(void* const* d_in, const int* in_sizes, int n_in,
                              void* d_out, int out_size) {
    const float* x   = (const float*)d_in[0];
    const float* w0  = (const float*)d_in[1];
    const float* b0  = (const float*)d_in[2];
    const float* g0  = (const float*)d_in[3];
    const float* be0 = (const float*)d_in[4];
    const float* w1  = (const float*)d_in[5];
    const float* b1  = (const float*)d_in[6];
    const float* g1  = (const float*)d_in[7];
    const float* be1 = (const float*)d_in[8];
    const float* fcw = (const float*)d_in[9];
    const float* fcb = (const float*)d_in[10];
    float* out = (float*)d_out;

    const int smem0 = (3072 + 192 * 128 + 512) * (int)sizeof(float);  // 112640 B
    cudaFuncSetAttribute(conv0_kernel, cudaFuncAttributeMaxDynamicSharedMemorySize, smem0);
    const int smemFC = 4 * 128 * FPITCH * 2;                          // 73728 B
    cudaFuncSetAttribute(fc_mma_kernel, cudaFuncAttributeMaxDynamicSharedMemorySize, smemFC);

    conv0_kernel<<<dim3(55, 55), 128, smem0>>>(x, w0, b0);
    ln2_kernel<<<128, 256>>>(0);
    norm_pool_kernel<<<(BSZ * 110 * 110 + 255) / 256, 256>>>(g0, be0);
    conv1_kernel<<<dim3(53, 53), 128>>>(w1, b1);
    ln2_kernel<<<128, 256>>>(1);
    norm1t_kernel<<<396, 256>>>(g1, be1);
    fc_mma_kernel<<<dim3(8, SK2), 256, smemFC>>>(fcw);
    softmax_kernel<<<128, 256>>>(fcb, out);
}

// round 9
// speedup vs baseline: 1.3587x; 1.0829x over previous
#include <cuda_runtime.h>
#include <cuda_bf16.h>
#include <cstdint>

typedef unsigned long long ull;

__device__ __forceinline__ ull dup2(float x) {
    ull r; asm("mov.b64 %0, {%1, %1};" : "=l"(r) : "f"(x)); return r;
}
__device__ __forceinline__ void fma2(ull& d, ull a, ull b) {
    asm("fma.rn.f32x2 %0, %1, %2, %0;" : "+l"(d) : "l"(a), "l"(b));
}
__device__ __forceinline__ void unpk(ull v, float& lo, float& hi) {
    asm("mov.b64 {%0, %1}, %2;" : "=f"(lo), "=f"(hi) : "l"(v));
}
__device__ __forceinline__ uint32_t smem_u32(const void* p) {
    uint32_t a;
    asm("{ .reg .u64 tmp; cvta.to.shared.u64 tmp, %1; cvt.u32.u64 %0, tmp; }"
        : "=r"(a) : "l"(p));
    return a;
}
// pack two floats to bf16x2 (lo bits = a, hi bits = b)
__device__ __forceinline__ uint32_t pack_bf16x2(float a, float b) {
    uint32_t r;
    asm("cvt.rn.bf16x2.f32 %0, %1, %2;" : "=r"(r) : "f"(b), "f"(a));
    return r;
}
#define LDSM_X4(r, addr) \
    asm volatile("ldmatrix.sync.aligned.m8n8.x4.shared.b16 {%0,%1,%2,%3}, [%4];" \
                 : "=r"((r)[0]), "=r"((r)[1]), "=r"((r)[2]), "=r"((r)[3]) : "r"(addr))
#define MMA_BF16(c, a, b0v, b1v) \
    asm volatile("mma.sync.aligned.m16n8k16.row.col.f32.bf16.bf16.f32 " \
                 "{%0,%1,%2,%3}, {%4,%5,%6,%7}, {%8,%9}, {%0,%1,%2,%3};" \
                 : "+f"((c)[0]), "+f"((c)[1]), "+f"((c)[2]), "+f"((c)[3]) \
                 : "r"((a)[0]), "r"((a)[1]), "r"((a)[2]), "r"((a)[3]), \
                   "r"(b0v), "r"(b1v))

#define BSZ 128
#define FCK 25281
#define KPAD 25344      // 18 * 22 * 64
#define SK2 18
#define NCHUNK 22
#define FPITCH 72       // fc smem pitch bf16 (144 B = 9*16B, odd granules)
#define CPB 400         // conv0 smem pitch bytes (200 bf16 = 25*16B, odd granules)

// scratch (no allocs allowed -> __device__ globals)
__device__ float g_y0[220 * 220 * BSZ];
__device__ float g_p0s[3025 * BSZ];
__device__ float g_p0ss[3025 * BSZ];
__device__ float g_m0[BSZ], g_r0[BSZ];
__device__ float g_h1[110 * 110 * BSZ];
__device__ float g_y1[159 * 159 * BSZ];
__device__ float g_p1s[2809 * BSZ];
__device__ float g_p1ss[2809 * BSZ];
__device__ float g_m1[BSZ], g_r1[BSZ];
__device__ uint4 g_fT_hi[(size_t)BSZ * KPAD / 8];  // feat hi bf16, [b][k]
__device__ uint4 g_fT_lo[(size_t)BSZ * KPAD / 8];  // feat lo bf16, [b][k]
__device__ float g_part[SK2 * BSZ * 1000];

// ---------------------------------------------------------------------------
// conv0_mma: per-location 128(b) x 16(oc) x 192(k) GEMM on HMMA, bf16 hi/lo
// split (drop lo*lo). grid (55,55), 128 threads (4 warps; warp w = 32 b rows).
// smem: Ph/Pl [128 b][200 bf16], Wh/Wl [16 oc][200 bf16]  -> 115200 B, 2/SM.
// Epilogue: bias+relu+HWB scatter + LN partials via shuffle (no smem).
// ---------------------------------------------------------------------------
__global__ void __launch_bounds__(128) conv0_mma_kernel(const float* __restrict__ x,
                                                        const float* __restrict__ w0,
                                                        const float* __restrict__ b0) {
    extern __shared__ __align__(16) char csb[];
    const uint32_t base = smem_u32(csb);
    const uint32_t PH = 0, PL = 128 * CPB, WH = 2 * 128 * CPB, WL = WH + 16 * CPB;
    const int i = blockIdx.x, j = blockIdx.y, t = threadIdx.x;

    // ---- stage patches: thread t owns batch b=t; 24 (c,di) rows of 8 k ----
#pragma unroll 4
    for (int p = 0; p < 24; p++) {
        int c = p >> 3, di = p & 7;
        const float* src = x + (((size_t)(t * 3 + c) * 224) + (i * 4 + di)) * 224 + j * 4;
        float4 fa = *(const float4*)src;
        float4 fb = *(const float4*)(src + 4);
        uint32_t h0 = pack_bf16x2(fa.x, fa.y), h1 = pack_bf16x2(fa.z, fa.w);
        uint32_t h2 = pack_bf16x2(fb.x, fb.y), h3 = pack_bf16x2(fb.z, fb.w);
        uint32_t l0 = pack_bf16x2(fa.x - __uint_as_float(h0 << 16),
                                  fa.y - __uint_as_float(h0 & 0xFFFF0000u));
        uint32_t l1 = pack_bf16x2(fa.z - __uint_as_float(h1 << 16),
                                  fa.w - __uint_as_float(h1 & 0xFFFF0000u));
        uint32_t l2 = pack_bf16x2(fb.x - __uint_as_float(h2 << 16),
                                  fb.y - __uint_as_float(h2 & 0xFFFF0000u));
        uint32_t l3 = pack_bf16x2(fb.z - __uint_as_float(h3 << 16),
                                  fb.w - __uint_as_float(h3 & 0xFFFF0000u));
        uint32_t off = (uint32_t)t * CPB + (uint32_t)(c * 64 + di * 8) * 2;
        *(uint4*)(csb + PH + off) = make_uint4(h0, h1, h2, h3);
        *(uint4*)(csb + PL + off) = make_uint4(l0, l1, l2, l3);
    }
    // ---- stage weights: 1536 float2, 12 per thread ----
    const float2* wloc = (const float2*)(w0 + (size_t)(i * 55 + j) * 3072);
#pragma unroll
    for (int p = 0; p < 12; p++) {
        int e2 = p * 128 + t;                 // 0..1535
        int oc = e2 / 96, kk = (e2 % 96) * 2;
        float2 wv = wloc[e2];
        uint32_t ph = pack_bf16x2(wv.x, wv.y);
        uint32_t pl = pack_bf16x2(wv.x - __uint_as_float(ph << 16),
                                  wv.y - __uint_as_float(ph & 0xFFFF0000u));
        uint32_t off = (uint32_t)oc * CPB + (uint32_t)kk * 2;
        *(uint32_t*)(csb + WH + off) = ph;
        *(uint32_t*)(csb + WL + off) = pl;
    }
    __syncthreads();

    const int wid = t >> 5, lane = t & 31;
    const int g = lane >> 2, tg = lane & 3;
    const int tq = lane >> 3, tr = lane & 7;
    const int mbase = wid * 32;

    float acc[2][2][4];
#pragma unroll
    for (int mt = 0; mt < 2; mt++)
#pragma unroll
        for (int nt = 0; nt < 2; nt++)
#pragma unroll
            for (int q = 0; q < 4; q++) acc[mt][nt][q] = 0.f;

    const uint32_t raBase = (uint32_t)(mbase + (tq & 1) * 8 + tr) * CPB + (tq >> 1) * 16;
    const uint32_t rbBase = (uint32_t)((tq & 2) * 4 + tr) * CPB + (tq & 1) * 16;

#pragma unroll
    for (int kk = 0; kk < 12; kk++) {
        const uint32_t kb = kk * 32;
        uint32_t bh[4], bl[4], ah0[4], ah1[4], al0[4], al1[4];
        LDSM_X4(bh, base + WH + rbBase + kb);
        LDSM_X4(bl, base + WL + rbBase + kb);
        LDSM_X4(ah0, base + PH + raBase + kb);
        LDSM_X4(al0, base + PL + raBase + kb);
        LDSM_X4(ah1, base + PH + raBase + 16 * CPB + kb);
        LDSM_X4(al1, base + PL + raBase + 16 * CPB + kb);
        // hi*hi
        MMA_BF16(acc[0][0], ah0, bh[0], bh[1]); MMA_BF16(acc[0][1], ah0, bh[2], bh[3]);
        MMA_BF16(acc[1][0], ah1, bh[0], bh[1]); MMA_BF16(acc[1][1], ah1, bh[2], bh[3]);
        // hi*lo
        MMA_BF16(acc[0][0], ah0, bl[0], bl[1]); MMA_BF16(acc[0][1], ah0, bl[2], bl[3]);
        MMA_BF16(acc[1][0], ah1, bl[0], bl[1]); MMA_BF16(acc[1][1], ah1, bl[2], bl[3]);
        // lo*hi
        MMA_BF16(acc[0][0], al0, bh[0], bh[1]); MMA_BF16(acc[0][1], al0, bh[2], bh[3]);
        MMA_BF16(acc[1][0], al1, bh[0], bh[1]); MMA_BF16(acc[1][1], al1, bh[2], bh[3]);
    }

    // ---- epilogue: bias + relu + HWB scatter + LN partials (shuffle) ----
    int ocs[4] = {2 * tg, 2 * tg + 1, 8 + 2 * tg, 9 + 2 * tg};
    float bias[4];
#pragma unroll
    for (int q = 0; q < 4; q++) bias[q] = b0[(ocs[q] * 55 + i) * 55 + j];
    const int blk = j * 55 + i;

#pragma unroll
    for (int mt = 0; mt < 2; mt++)
#pragma unroll
        for (int rh = 0; rh < 2; rh++) {
            int b = mbase + mt * 16 + rh * 8 + g;
            float vals[4] = {acc[mt][0][2 * rh], acc[mt][0][2 * rh + 1],
                             acc[mt][1][2 * rh], acc[mt][1][2 * rh + 1]};
            float s = 0.f, ss = 0.f;
#pragma unroll
            for (int q = 0; q < 4; q++) {
                float v = fmaxf(vals[q] + bias[q], 0.f);
                int oc = ocs[q];
                g_y0[((i * 4 + (oc >> 2)) * 220 + (j * 4 + (oc & 3))) * 128 + b] = v;
                s += v;
                ss = fmaf(v, v, ss);
            }
            s  += __shfl_xor_sync(0xffffffffu, s, 1);
            s  += __shfl_xor_sync(0xffffffffu, s, 2);
            ss += __shfl_xor_sync(0xffffffffu, ss, 1);
            ss += __shfl_xor_sync(0xffffffffu, ss, 2);
            if (tg == 0) {
                g_p0s[blk * 128 + b]  = s;
                g_p0ss[blk * 128 + b] = ss;
            }
        }
}

// ---------------------------------------------------------------------------
// reduce LN partials -> mean, rstd
// ---------------------------------------------------------------------------
__global__ void ln2_kernel(int which) {
    const float* ps  = which ? g_p1s  : g_p0s;
    const float* pss = which ? g_p1ss : g_p0ss;
    float* gm        = which ? g_m1 : g_m0;
    float* gr        = which ? g_r1 : g_r0;
    const int nblk   = which ? 2809 : 3025;
    const float invn = which ? (1.f / 25281.f) : (1.f / 48400.f);
    int b = blockIdx.x, t = threadIdx.x;
    float s = 0.f, ss = 0.f;
    for (int k = t; k < nblk; k += 256) {
        s  += ps[k * 128 + b];
        ss += pss[k * 128 + b];
    }
    __shared__ float r1[8], r2[8];
    for (int o = 16; o; o >>= 1) {
        s  += __shfl_xor_sync(0xffffffffu, s, o);
        ss += __shfl_xor_sync(0xffffffffu, ss, o);
    }
    if ((t & 31) == 0) { r1[t >> 5] = s; r2[t >> 5] = ss; }
    __syncthreads();
    if (t == 0) {
        s = 0.f; ss = 0.f;
        for (int w = 0; w < 8; w++) { s += r1[w]; ss += r2[w]; }
        float m = s * invn;
        float var = ss * invn - m * m;
        gm[b] = m;
        gr[b] = rsqrtf(var + 1e-5f);
    }
}

// ---------------------------------------------------------------------------
// normalize (layer0) + 2x2 maxpool -> g_h1 [pos][b]
// ---------------------------------------------------------------------------
__global__ void norm_pool_kernel(const float* __restrict__ g0,
                                 const float* __restrict__ be0) {
    int idx = blockIdx.x * 256 + threadIdx.x;
    if (idx >= BSZ * 110 * 110) return;
    int b = idx & 127, pos = idx >> 7;
    int r = pos / 110, c = pos - r * 110;
    float m = g_m0[b], rs = g_r0[b];
    float mx = -3.4e38f;
#pragma unroll
    for (int dr = 0; dr < 2; dr++)
#pragma unroll
        for (int dc = 0; dc < 2; dc++) {
            int P = (2 * r + dr) * 220 + 2 * c + dc;
            float v = (g_y0[P * 128 + b] - m) * rs * g0[P] + be0[P];
            mx = fmaxf(mx, v);
        }
    g_h1[pos * 128 + b] = mx;
}

// ---------------------------------------------------------------------------
// conv1 [R3-proven]: local conv 1x6x6 s2, 9oc, bias+relu, HWB, LN partials
// ---------------------------------------------------------------------------
__global__ void conv1_kernel(const float* __restrict__ w1,
                             const float* __restrict__ b1) {
    __shared__ float Ws2[36 * 10];
    __shared__ float P2[36 * 128];
    int i = blockIdx.x, j = blockIdx.y, t = threadIdx.x;
    const float* wloc = w1 + (i * 53 + j) * 324;
    for (int e = t; e < 324; e += 128) {
        int oc = e / 36, k = e - oc * 36;
        Ws2[k * 10 + oc] = wloc[e];
    }
    for (int e = t; e < 36 * 128; e += 128) {
        int b = e & 127, kk = e >> 7;
        int di = kk / 6, dj = kk - di * 6;
        P2[kk * 128 + b] = g_h1[((2 * i + di) * 110 + 2 * j + dj) * 128 + b];
    }
    __syncthreads();

    ull a[4] = {0ull, 0ull, 0ull, 0ull};
    float a8 = 0.f;
#pragma unroll 4
    for (int k = 0; k < 36; k++) {
        float xv = P2[k * 128 + t];
        ull xd = dup2(xv);
        const ull* wp = (const ull*)&Ws2[k * 10];
        fma2(a[0], xd, wp[0]);
        fma2(a[1], xd, wp[1]);
        fma2(a[2], xd, wp[2]);
        fma2(a[3], xd, wp[3]);
        a8 = fmaf(xv, Ws2[k * 10 + 8], a8);
    }
    float v[9];
    unpk(a[0], v[0], v[1]); unpk(a[1], v[2], v[3]);
    unpk(a[2], v[4], v[5]); unpk(a[3], v[6], v[7]);
    v[8] = a8;
    float s = 0.f, ss = 0.f;
#pragma unroll
    for (int oc = 0; oc < 9; oc++) {
        float val = fmaxf(v[oc] + b1[(oc * 53 + i) * 53 + j], 0.f);
        int row = i * 3 + oc / 3, col = j * 3 + oc % 3;
        g_y1[(row * 159 + col) * 128 + t] = val;
        s += val;
        ss = fmaf(val, val, ss);
    }
    int blk = blockIdx.y * 53 + blockIdx.x;
    g_p1s[blk * 128 + t]  = s;
    g_p1ss[blk * 128 + t] = ss;
}

// ---------------------------------------------------------------------------
// norm1t: normalize layer1 + transpose to [b][k] + bf16 hi/lo split.
// grid 396 (64-k tiles), 256 threads.
// ---------------------------------------------------------------------------
__global__ void __launch_bounds__(256) norm1t_kernel(const float* __restrict__ g1,
                                                     const float* __restrict__ be1) {
    __shared__ float Tb[64][129];
    const int k0 = blockIdx.x * 64;
    const int t = threadIdx.x;
#pragma unroll
    for (int p = 0; p < 8; p++) {
        int e = p * 256 + t;
        int kl = e >> 5, bq = e & 31;
        int k = k0 + kl;
        float4 v = make_float4(0.f, 0.f, 0.f, 0.f);
        if (k < FCK) {
            float4 y = *(const float4*)&g_y1[k * 128 + bq * 4];
            float4 m = *(const float4*)&g_m1[bq * 4];
            float4 r = *(const float4*)&g_r1[bq * 4];
            float gk = g1[k], bk = be1[k];
            v.x = fmaf((y.x - m.x) * r.x, gk, bk);
            v.y = fmaf((y.y - m.y) * r.y, gk, bk);
            v.z = fmaf((y.z - m.z) * r.z, gk, bk);
            v.w = fmaf((y.w - m.w) * r.w, gk, bk);
        }
        Tb[kl][bq * 4 + 0] = v.x;
        Tb[kl][bq * 4 + 1] = v.y;
        Tb[kl][bq * 4 + 2] = v.z;
        Tb[kl][bq * 4 + 3] = v.w;
    }
    __syncthreads();

    const int b = t >> 1, half = t & 1;
    uint32_t oh[16], ol[16];
#pragma unroll
    for (int u = 0; u < 16; u++) {
        float v0 = Tb[half * 32 + 2 * u][b];
        float v1 = Tb[half * 32 + 2 * u + 1][b];
        uint32_t ph = pack_bf16x2(v0, v1);           // lo=v0, hi=v1
        float h0 = __uint_as_float(ph << 16);
        float h1 = __uint_as_float(ph & 0xFFFF0000u);
        oh[u] = ph;
        ol[u] = pack_bf16x2(v0 - h0, v1 - h1);
    }
    uint32_t* dh = (uint32_t*)g_fT_hi + (size_t)b * (KPAD / 2) + (k0 + half * 32) / 2;
    uint32_t* dl = (uint32_t*)g_fT_lo + (size_t)b * (KPAD / 2) + (k0 + half * 32) / 2;
#pragma unroll
    for (int q = 0; q < 4; q++) {
        ((uint4*)dh)[q] = make_uint4(oh[4 * q], oh[4 * q + 1], oh[4 * q + 2], oh[4 * q + 3]);
        ((uint4*)dl)[q] = make_uint4(ol[4 * q], ol[4 * q + 1], ol[4 * q + 2], ol[4 * q + 3]);
    }
}

// ---------------------------------------------------------------------------
// fc_mma [R8-proven]: bf16 hi/lo-split GEMM on mma.sync (HMMA).
// grid (8, 18), 256 threads (8 warps).
// ---------------------------------------------------------------------------
__global__ void __launch_bounds__(256) fc_mma_kernel(const float* __restrict__ fcw) {
    extern __shared__ __align__(16) __nv_bfloat16 sb[];
    __nv_bfloat16* Wh = sb;                  // [128][72]
    __nv_bfloat16* Wl = Wh + 128 * FPITCH;
    __nv_bfloat16* Fh = Wl + 128 * FPITCH;
    __nv_bfloat16* Fl = Fh + 128 * FPITCH;
    const uint32_t base = smem_u32(sb);
    const uint32_t WH_OFF = 0, WL_OFF = 128 * FPITCH * 2,
                   FH_OFF = 2 * 128 * FPITCH * 2, FL_OFF = 3 * 128 * FPITCH * 2;

    const int t = threadIdx.x, wid = t >> 5, lane = t & 31;
    const int g = lane >> 2, tg = lane & 3;
    const int tq = lane >> 3, tr = lane & 7;
    const int nbase = blockIdx.x * 128;
    const int sk = blockIdx.y;

    float acc[16][4];
#pragma unroll
    for (int bt = 0; bt < 16; bt++)
#pragma unroll
        for (int q = 0; q < 4; q++) acc[bt][q] = 0.f;

    const uint32_t aRow = wid * 16 + (tq & 1) * 8 + tr;
    const uint32_t aKof = (tq >> 1) * 8;
    const uint32_t bRowB = (tq & 2) * 4 + tr;
    const uint32_t bKof = (tq & 1) * 8;

    for (int it = 0; it < NCHUNK; it++) {
        const int k0 = (sk * NCHUNK + it) * 64;
        __syncthreads();
#pragma unroll 4
        for (int p = 0; p < 32; p++) {
            int e = p * 256 + t;
            int row = e >> 6, c = e & 63;
            int ng = nbase + row, k = k0 + c;
            float v = (ng < 1000 && k < FCK) ? __ldg(&fcw[ng * FCK + k]) : 0.f;
            __nv_bfloat16 h = __float2bfloat16(v);
            __nv_bfloat16 l = __float2bfloat16(v - __bfloat162float(h));
            Wh[row * FPITCH + c] = h;
            Wl[row * FPITCH + c] = l;
        }
#pragma unroll
        for (int p = 0; p < 4; p++) {
            int e = p * 256 + t;
            int b = e >> 3, q = e & 7;
            size_t idx = ((size_t)b * KPAD + k0) / 8 + q;
            *(uint4*)&Fh[b * FPITCH + q * 8] = g_fT_hi[idx];
            *(uint4*)&Fl[b * FPITCH + q * 8] = g_fT_lo[idx];
        }
        __syncthreads();

#pragma unroll
        for (int k16 = 0; k16 < 4; k16++) {
            uint32_t ak = (k16 * 16 + aKof) * 2;
            uint32_t ah[4], al[4];
            LDSM_X4(ah, base + WH_OFF + aRow * (FPITCH * 2) + ak);
            LDSM_X4(al, base + WL_OFF + aRow * (FPITCH * 2) + ak);
            uint32_t bk = (k16 * 16 + bKof) * 2;
#pragma unroll
            for (int bt2 = 0; bt2 < 8; bt2++) {
                uint32_t brow = bt2 * 16 + bRowB;
                uint32_t bh[4], bl[4];
                LDSM_X4(bh, base + FH_OFF + brow * (FPITCH * 2) + bk);
                LDSM_X4(bl, base + FL_OFF + brow * (FPITCH * 2) + bk);
                MMA_BF16(acc[2 * bt2],     ah, bh[0], bh[1]);
                MMA_BF16(acc[2 * bt2 + 1], ah, bh[2], bh[3]);
                MMA_BF16(acc[2 * bt2],     ah, bl[0], bl[1]);
                MMA_BF16(acc[2 * bt2 + 1], ah, bl[2], bl[3]);
                MMA_BF16(acc[2 * bt2],     al, bh[0], bh[1]);
                MMA_BF16(acc[2 * bt2 + 1], al, bh[2], bh[3]);
            }
        }
    }

    float* outp = g_part + sk * (BSZ * 1000);
    const int n0 = nbase + wid * 16 + g;
    const int n1 = n0 + 8;
#pragma unroll
    for (int bt = 0; bt < 16; bt++) {
        int b0 = bt * 8 + tg * 2;
        if (n0 < 1000) {
            outp[b0 * 1000 + n0]       = acc[bt][0];
            outp[(b0 + 1) * 1000 + n0] = acc[bt][1];
        }
        if (n1 < 1000) {
            outp[b0 * 1000 + n1]       = acc[bt][2];
            outp[(b0 + 1) * 1000 + n1] = acc[bt][3];
        }
    }
}

// ---------------------------------------------------------------------------
// reduce split-K partials (fixed order -> deterministic) + bias + softmax
// ---------------------------------------------------------------------------
__global__ void softmax_kernel(const float* __restrict__ fcb,
                               float* __restrict__ out) {
    int b = blockIdx.x, t = threadIdx.x;
    __shared__ float lg[1000];
    __shared__ float red[8];
    __shared__ float bc;

    for (int n = t; n < 1000; n += 256) {
        float v = fcb[n];
        for (int s = 0; s < SK2; s++) v += g_part[(s * BSZ + b) * 1000 + n];
        lg[n] = v;
    }
    __syncthreads();

    float mx = -3.4e38f;
    for (int n = t; n < 1000; n += 256) mx = fmaxf(mx, lg[n]);
    for (int o = 16; o; o >>= 1) mx = fmaxf(mx, __shfl_xor_sync(0xffffffffu, mx, o));
    if ((t & 31) == 0) red[t >> 5] = mx;
    __syncthreads();
    if (t == 0) {
        float m = red[0];
        for (int w = 1; w < 8; w++) m = fmaxf(m, red[w]);
        bc = m;
    }
    __syncthreads();
    mx = bc;

    float s = 0.f;
    for (int n = t; n < 1000; n += 256) s += expf(lg[n] - mx);
    for (int o = 16; o; o >>= 1) s += __shfl_xor_sync(0xffffffffu, s, o);
    __syncthreads();
    if ((t & 31) == 0) red[t >> 5] = s;
    __syncthreads();
    if (t == 0) {
        float tot = 0.f;
        for (int w = 0; w < 8; w++) tot += red[w];
        bc = 1.f / tot;
    }
    __syncthreads();
    float inv = bc;
    for (int n = t; n < 1000; n += 256)
        out[b * 1000 + n] = expf(lg[n] - mx) * inv;
}

// ---------------------------------------------------------------------------

extern "C" void kernel_launch(void* const* d_in, const int* in_sizes, int n_in,
                              void* d_out, int out_size) {
    const float* x   = (const float*)d_in[0];
    const float* w0  = (const float*)d_in[1];
    const float* b0  = (const float*)d_in[2];
    const float* g0  = (const float*)d_in[3];
    const float* be0 = (const float*)d_in[4];
    const float* w1  = (const float*)d_in[5];
    const float* b1  = (const float*)d_in[6];
    const float* g1  = (const float*)d_in[7];
    const float* be1 = (const float*)d_in[8];
    const float* fcw = (const float*)d_in[9];
    const float* fcb = (const float*)d_in[10];
    float* out = (float*)d_out;

    const int smem0 = 2 * 128 * CPB + 2 * 16 * CPB;                   // 115200 B
    cudaFuncSetAttribute(conv0_mma_kernel, cudaFuncAttributeMaxDynamicSharedMemorySize, smem0);
    const int smemFC = 4 * 128 * FPITCH * 2;                          // 73728 B
    cudaFuncSetAttribute(fc_mma_kernel, cudaFuncAttributeMaxDynamicSharedMemorySize, smemFC);

    conv0_mma_kernel<<<dim3(55, 55), 128, smem0>>>(x, w0, b0);
    ln2_kernel<<<128, 256>>>(0);
    norm_pool_kernel<<<(BSZ * 110 * 110 + 255) / 256, 256>>>(g0, be0);
    conv1_kernel<<<dim3(53, 53), 128>>>(w1, b1);
    ln2_kernel<<<128, 256>>>(1);
    norm1t_kernel<<<396, 256>>>(g1, be1);
    fc_mma_kernel<<<dim3(8, SK2), 256, smemFC>>>(fcw);
    softmax_kernel<<<128, 256>>>(fcb, out);
}

// round 10
// speedup vs baseline: 1.8655x; 1.3730x over previous
#include <cuda_runtime.h>
#include <cuda_bf16.h>
#include <cstdint>

typedef unsigned long long ull;

__device__ __forceinline__ ull dup2(float x) {
    ull r; asm("mov.b64 %0, {%1, %1};" : "=l"(r) : "f"(x)); return r;
}
__device__ __forceinline__ void fma2(ull& d, ull a, ull b) {
    asm("fma.rn.f32x2 %0, %1, %2, %0;" : "+l"(d) : "l"(a), "l"(b));
}
__device__ __forceinline__ void unpk(ull v, float& lo, float& hi) {
    asm("mov.b64 {%0, %1}, %2;" : "=f"(lo), "=f"(hi) : "l"(v));
}
__device__ __forceinline__ uint32_t smem_u32(const void* p) {
    uint32_t a;
    asm("{ .reg .u64 tmp; cvta.to.shared.u64 tmp, %1; cvt.u32.u64 %0, tmp; }"
        : "=r"(a) : "l"(p));
    return a;
}
// pack two floats to bf16x2 (lo bits = a, hi bits = b)
__device__ __forceinline__ uint32_t pack_bf16x2(float a, float b) {
    uint32_t r;
    asm("cvt.rn.bf16x2.f32 %0, %1, %2;" : "=r"(r) : "f"(b), "f"(a));
    return r;
}
#define LDSM_X4(r, addr) \
    asm volatile("ldmatrix.sync.aligned.m8n8.x4.shared.b16 {%0,%1,%2,%3}, [%4];" \
                 : "=r"((r)[0]), "=r"((r)[1]), "=r"((r)[2]), "=r"((r)[3]) : "r"(addr))
#define MMA_BF16(c, a, b0v, b1v) \
    asm volatile("mma.sync.aligned.m16n8k16.row.col.f32.bf16.bf16.f32 " \
                 "{%0,%1,%2,%3}, {%4,%5,%6,%7}, {%8,%9}, {%0,%1,%2,%3};" \
                 : "+f"((c)[0]), "+f"((c)[1]), "+f"((c)[2]), "+f"((c)[3]) \
                 : "r"((a)[0]), "r"((a)[1]), "r"((a)[2]), "r"((a)[3]), \
                   "r"(b0v), "r"(b1v))

#define BSZ 128
#define FCK 25281
#define KPAD 25344      // 18 * 22 * 64
#define SK2 18
#define NCHUNK 22
#define FPITCH 72       // fc smem pitch bf16 (144 B = 9*16B, odd granules)
#define CPB 400         // conv0 smem pitch bytes (200 bf16 = 25*16B, odd granules)

// scratch (no allocs allowed -> __device__ globals)
__device__ float g_y0[220 * 220 * BSZ];
__device__ float g_p0s[3025 * BSZ];
__device__ float g_p0ss[3025 * BSZ];
__device__ float g_m0[BSZ], g_r0[BSZ];
__device__ float g_h1[110 * 110 * BSZ];
__device__ float g_y1[159 * 159 * BSZ];
__device__ float g_p1s[2809 * BSZ];
__device__ float g_p1ss[2809 * BSZ];
__device__ float g_m1[BSZ], g_r1[BSZ];
__device__ uint4 g_fT_hi[(size_t)BSZ * KPAD / 8];  // feat hi bf16, [b][k]
__device__ uint4 g_fT_lo[(size_t)BSZ * KPAD / 8];  // feat lo bf16, [b][k]
__device__ float g_part[SK2 * BSZ * 1000];

// ---------------------------------------------------------------------------
// conv0_mma: per-location 128(b) x 16(oc) x 192(k) GEMM on HMMA, bf16 hi/lo
// split (drop lo*lo). grid (55,55), 256 threads (8 warps; warp w = 16 b rows).
// smem: Ph/Pl [128 b][200 bf16], Wh/Wl [16 oc][200 bf16] -> 115200 B, 2/SM
// (16 warps/SM). Epilogue: bias+relu+HWB scatter + LN partials via shuffle.
// ---------------------------------------------------------------------------
__global__ void __launch_bounds__(256) conv0_mma_kernel(const float* __restrict__ x,
                                                        const float* __restrict__ w0,
                                                        const float* __restrict__ b0) {
    extern __shared__ __align__(16) char csb[];
    const uint32_t base = smem_u32(csb);
    const uint32_t PH = 0, PL = 128 * CPB, WH = 2 * 128 * CPB, WL = WH + 16 * CPB;
    const int i = blockIdx.x, j = blockIdx.y, t = threadIdx.x;

    // ---- stage patches: thread t owns batch b=t&127; 12 (c,di) rows each ----
    {
        const int b = t & 127, hp = t >> 7;   // hp: row half
#pragma unroll 4
        for (int p = 0; p < 12; p++) {
            int p2 = hp * 12 + p;
            int c = p2 >> 3, di = p2 & 7;
            const float* src = x + (((size_t)(b * 3 + c) * 224) + (i * 4 + di)) * 224 + j * 4;
            float4 fa = *(const float4*)src;
            float4 fb = *(const float4*)(src + 4);
            uint32_t h0 = pack_bf16x2(fa.x, fa.y), h1 = pack_bf16x2(fa.z, fa.w);
            uint32_t h2 = pack_bf16x2(fb.x, fb.y), h3 = pack_bf16x2(fb.z, fb.w);
            uint32_t l0 = pack_bf16x2(fa.x - __uint_as_float(h0 << 16),
                                      fa.y - __uint_as_float(h0 & 0xFFFF0000u));
            uint32_t l1 = pack_bf16x2(fa.z - __uint_as_float(h1 << 16),
                                      fa.w - __uint_as_float(h1 & 0xFFFF0000u));
            uint32_t l2 = pack_bf16x2(fb.x - __uint_as_float(h2 << 16),
                                      fb.y - __uint_as_float(h2 & 0xFFFF0000u));
            uint32_t l3 = pack_bf16x2(fb.z - __uint_as_float(h3 << 16),
                                      fb.w - __uint_as_float(h3 & 0xFFFF0000u));
            uint32_t off = (uint32_t)b * CPB + (uint32_t)(c * 64 + di * 8) * 2;
            *(uint4*)(csb + PH + off) = make_uint4(h0, h1, h2, h3);
            *(uint4*)(csb + PL + off) = make_uint4(l0, l1, l2, l3);
        }
    }
    // ---- stage weights: 1536 float2, 6 per thread ----
    const float2* wloc = (const float2*)(w0 + (size_t)(i * 55 + j) * 3072);
#pragma unroll
    for (int p = 0; p < 6; p++) {
        int e2 = p * 256 + t;                 // 0..1535
        int oc = e2 / 96, kk = (e2 % 96) * 2;
        float2 wv = wloc[e2];
        uint32_t ph = pack_bf16x2(wv.x, wv.y);
        uint32_t pl = pack_bf16x2(wv.x - __uint_as_float(ph << 16),
                                  wv.y - __uint_as_float(ph & 0xFFFF0000u));
        uint32_t off = (uint32_t)oc * CPB + (uint32_t)kk * 2;
        *(uint32_t*)(csb + WH + off) = ph;
        *(uint32_t*)(csb + WL + off) = pl;
    }
    __syncthreads();

    const int wid = t >> 5, lane = t & 31;
    const int g = lane >> 2, tg = lane & 3;
    const int tq = lane >> 3, tr = lane & 7;
    const int mbase = wid * 16;

    float acc[2][4];
#pragma unroll
    for (int nt = 0; nt < 2; nt++)
#pragma unroll
        for (int q = 0; q < 4; q++) acc[nt][q] = 0.f;

    const uint32_t raBase = (uint32_t)(mbase + (tq & 1) * 8 + tr) * CPB + (tq >> 1) * 16;
    const uint32_t rbBase = (uint32_t)((tq & 2) * 4 + tr) * CPB + (tq & 1) * 16;

#pragma unroll
    for (int kk = 0; kk < 12; kk++) {
        const uint32_t kb = kk * 32;
        uint32_t bh[4], bl[4], ah[4], al[4];
        LDSM_X4(bh, base + WH + rbBase + kb);
        LDSM_X4(bl, base + WL + rbBase + kb);
        LDSM_X4(ah, base + PH + raBase + kb);
        LDSM_X4(al, base + PL + raBase + kb);
        MMA_BF16(acc[0], ah, bh[0], bh[1]); MMA_BF16(acc[1], ah, bh[2], bh[3]);
        MMA_BF16(acc[0], ah, bl[0], bl[1]); MMA_BF16(acc[1], ah, bl[2], bl[3]);
        MMA_BF16(acc[0], al, bh[0], bh[1]); MMA_BF16(acc[1], al, bh[2], bh[3]);
    }

    // ---- epilogue: bias + relu + HWB scatter + LN partials (shuffle) ----
    int ocs[4] = {2 * tg, 2 * tg + 1, 8 + 2 * tg, 9 + 2 * tg};
    float bias[4];
#pragma unroll
    for (int q = 0; q < 4; q++) bias[q] = b0[(ocs[q] * 55 + i) * 55 + j];
    const int blk = j * 55 + i;

#pragma unroll
    for (int rh = 0; rh < 2; rh++) {
        int b = mbase + rh * 8 + g;
        float vals[4] = {acc[0][2 * rh], acc[0][2 * rh + 1],
                         acc[1][2 * rh], acc[1][2 * rh + 1]};
        float s = 0.f, ss = 0.f;
#pragma unroll
        for (int q = 0; q < 4; q++) {
            float v = fmaxf(vals[q] + bias[q], 0.f);
            int oc = ocs[q];
            g_y0[((i * 4 + (oc >> 2)) * 220 + (j * 4 + (oc & 3))) * 128 + b] = v;
            s += v;
            ss = fmaf(v, v, ss);
        }
        s  += __shfl_xor_sync(0xffffffffu, s, 1);
        s  += __shfl_xor_sync(0xffffffffu, s, 2);
        ss += __shfl_xor_sync(0xffffffffu, ss, 1);
        ss += __shfl_xor_sync(0xffffffffu, ss, 2);
        if (tg == 0) {
            g_p0s[blk * 128 + b]  = s;
            g_p0ss[blk * 128 + b] = ss;
        }
    }
}

// ---------------------------------------------------------------------------
// reduce LN partials -> mean, rstd
// ---------------------------------------------------------------------------
__global__ void ln2_kernel(int which) {
    const float* ps  = which ? g_p1s  : g_p0s;
    const float* pss = which ? g_p1ss : g_p0ss;
    float* gm        = which ? g_m1 : g_m0;
    float* gr        = which ? g_r1 : g_r0;
    const int nblk   = which ? 2809 : 3025;
    const float invn = which ? (1.f / 25281.f) : (1.f / 48400.f);
    int b = blockIdx.x, t = threadIdx.x;
    float s = 0.f, ss = 0.f;
    for (int k = t; k < nblk; k += 256) {
        s  += ps[k * 128 + b];
        ss += pss[k * 128 + b];
    }
    __shared__ float r1[8], r2[8];
    for (int o = 16; o; o >>= 1) {
        s  += __shfl_xor_sync(0xffffffffu, s, o);
        ss += __shfl_xor_sync(0xffffffffu, ss, o);
    }
    if ((t & 31) == 0) { r1[t >> 5] = s; r2[t >> 5] = ss; }
    __syncthreads();
    if (t == 0) {
        s = 0.f; ss = 0.f;
        for (int w = 0; w < 8; w++) { s += r1[w]; ss += r2[w]; }
        float m = s * invn;
        float var = ss * invn - m * m;
        gm[b] = m;
        gr[b] = rsqrtf(var + 1e-5f);
    }
}

// ---------------------------------------------------------------------------
// normalize (layer0) + 2x2 maxpool -> g_h1 [pos][b]
// ---------------------------------------------------------------------------
__global__ void norm_pool_kernel(const float* __restrict__ g0,
                                 const float* __restrict__ be0) {
    int idx = blockIdx.x * 256 + threadIdx.x;
    if (idx >= BSZ * 110 * 110) return;
    int b = idx & 127, pos = idx >> 7;
    int r = pos / 110, c = pos - r * 110;
    float m = g_m0[b], rs = g_r0[b];
    float mx = -3.4e38f;
#pragma unroll
    for (int dr = 0; dr < 2; dr++)
#pragma unroll
        for (int dc = 0; dc < 2; dc++) {
            int P = (2 * r + dr) * 220 + 2 * c + dc;
            float v = (g_y0[P * 128 + b] - m) * rs * g0[P] + be0[P];
            mx = fmaxf(mx, v);
        }
    g_h1[pos * 128 + b] = mx;
}

// ---------------------------------------------------------------------------
// conv1 [R3-proven]: local conv 1x6x6 s2, 9oc, bias+relu, HWB, LN partials
// ---------------------------------------------------------------------------
__global__ void conv1_kernel(const float* __restrict__ w1,
                             const float* __restrict__ b1) {
    __shared__ float Ws2[36 * 10];
    __shared__ float P2[36 * 128];
    int i = blockIdx.x, j = blockIdx.y, t = threadIdx.x;
    const float* wloc = w1 + (i * 53 + j) * 324;
    for (int e = t; e < 324; e += 128) {
        int oc = e / 36, k = e - oc * 36;
        Ws2[k * 10 + oc] = wloc[e];
    }
    for (int e = t; e < 36 * 128; e += 128) {
        int b = e & 127, kk = e >> 7;
        int di = kk / 6, dj = kk - di * 6;
        P2[kk * 128 + b] = g_h1[((2 * i + di) * 110 + 2 * j + dj) * 128 + b];
    }
    __syncthreads();

    ull a[4] = {0ull, 0ull, 0ull, 0ull};
    float a8 = 0.f;
#pragma unroll 4
    for (int k = 0; k < 36; k++) {
        float xv = P2[k * 128 + t];
        ull xd = dup2(xv);
        const ull* wp = (const ull*)&Ws2[k * 10];
        fma2(a[0], xd, wp[0]);
        fma2(a[1], xd, wp[1]);
        fma2(a[2], xd, wp[2]);
        fma2(a[3], xd, wp[3]);
        a8 = fmaf(xv, Ws2[k * 10 + 8], a8);
    }
    float v[9];
    unpk(a[0], v[0], v[1]); unpk(a[1], v[2], v[3]);
    unpk(a[2], v[4], v[5]); unpk(a[3], v[6], v[7]);
    v[8] = a8;
    float s = 0.f, ss = 0.f;
#pragma unroll
    for (int oc = 0; oc < 9; oc++) {
        float val = fmaxf(v[oc] + b1[(oc * 53 + i) * 53 + j], 0.f);
        int row = i * 3 + oc / 3, col = j * 3 + oc % 3;
        g_y1[(row * 159 + col) * 128 + t] = val;
        s += val;
        ss = fmaf(val, val, ss);
    }
    int blk = blockIdx.y * 53 + blockIdx.x;
    g_p1s[blk * 128 + t]  = s;
    g_p1ss[blk * 128 + t] = ss;
}

// ---------------------------------------------------------------------------
// norm1t: normalize layer1 + transpose to [b][k] + bf16 hi/lo split.
// grid 396 (64-k tiles), 256 threads.
// ---------------------------------------------------------------------------
__global__ void __launch_bounds__(256) norm1t_kernel(const float* __restrict__ g1,
                                                     const float* __restrict__ be1) {
    __shared__ float Tb[64][129];
    const int k0 = blockIdx.x * 64;
    const int t = threadIdx.x;
#pragma unroll
    for (int p = 0; p < 8; p++) {
        int e = p * 256 + t;
        int kl = e >> 5, bq = e & 31;
        int k = k0 + kl;
        float4 v = make_float4(0.f, 0.f, 0.f, 0.f);
        if (k < FCK) {
            float4 y = *(const float4*)&g_y1[k * 128 + bq * 4];
            float4 m = *(const float4*)&g_m1[bq * 4];
            float4 r = *(const float4*)&g_r1[bq * 4];
            float gk = g1[k], bk = be1[k];
            v.x = fmaf((y.x - m.x) * r.x, gk, bk);
            v.y = fmaf((y.y - m.y) * r.y, gk, bk);
            v.z = fmaf((y.z - m.z) * r.z, gk, bk);
            v.w = fmaf((y.w - m.w) * r.w, gk, bk);
        }
        Tb[kl][bq * 4 + 0] = v.x;
        Tb[kl][bq * 4 + 1] = v.y;
        Tb[kl][bq * 4 + 2] = v.z;
        Tb[kl][bq * 4 + 3] = v.w;
    }
    __syncthreads();

    const int b = t >> 1, half = t & 1;
    uint32_t oh[16], ol[16];
#pragma unroll
    for (int u = 0; u < 16; u++) {
        float v0 = Tb[half * 32 + 2 * u][b];
        float v1 = Tb[half * 32 + 2 * u + 1][b];
        uint32_t ph = pack_bf16x2(v0, v1);           // lo=v0, hi=v1
        float h0 = __uint_as_float(ph << 16);
        float h1 = __uint_as_float(ph & 0xFFFF0000u);
        oh[u] = ph;
        ol[u] = pack_bf16x2(v0 - h0, v1 - h1);
    }
    uint32_t* dh = (uint32_t*)g_fT_hi + (size_t)b * (KPAD / 2) + (k0 + half * 32) / 2;
    uint32_t* dl = (uint32_t*)g_fT_lo + (size_t)b * (KPAD / 2) + (k0 + half * 32) / 2;
#pragma unroll
    for (int q = 0; q < 4; q++) {
        ((uint4*)dh)[q] = make_uint4(oh[4 * q], oh[4 * q + 1], oh[4 * q + 2], oh[4 * q + 3]);
        ((uint4*)dl)[q] = make_uint4(ol[4 * q], ol[4 * q + 1], ol[4 * q + 2], ol[4 * q + 3]);
    }
}

// ---------------------------------------------------------------------------
// fc_mma: bf16 hi/lo-split GEMM on mma.sync, software-pipelined:
// tile it+1's gmem loads (fcw f32 + feat bf16) sit in registers while tile
// it's MMAs run. grid (8, 18), 256 threads (8 warps).
// ---------------------------------------------------------------------------
__global__ void __launch_bounds__(256) fc_mma_kernel(const float* __restrict__ fcw) {
    extern __shared__ __align__(16) __nv_bfloat16 sb[];
    __nv_bfloat16* Wh = sb;                  // [128][72]
    __nv_bfloat16* Wl = Wh + 128 * FPITCH;
    __nv_bfloat16* Fh = Wl + 128 * FPITCH;
    __nv_bfloat16* Fl = Fh + 128 * FPITCH;
    const uint32_t base = smem_u32(sb);
    const uint32_t WH_OFF = 0, WL_OFF = 128 * FPITCH * 2,
                   FH_OFF = 2 * 128 * FPITCH * 2, FL_OFF = 3 * 128 * FPITCH * 2;

    const int t = threadIdx.x, wid = t >> 5, lane = t & 31;
    const int g = lane >> 2, tg = lane & 3;
    const int tq = lane >> 3, tr = lane & 7;
    const int nbase = blockIdx.x * 128;
    const int sk = blockIdx.y;

    float acc[16][4];
#pragma unroll
    for (int bt = 0; bt < 16; bt++)
#pragma unroll
        for (int q = 0; q < 4; q++) acc[bt][q] = 0.f;

    const uint32_t aRow = wid * 16 + (tq & 1) * 8 + tr;
    const uint32_t aKof = (tq >> 1) * 8;
    const uint32_t bRowB = (tq & 2) * 4 + tr;
    const uint32_t bKof = (tq & 1) * 8;

    // load-to-register staging (prefetch registers)
    float wv[32];
    uint4 fh[4], fl[4];
    const int wrow = t >> 6, wc0 = (t & 63);  // thread covers rows wrow, wrow+4, ...
    const int frow = t >> 3, fq = t & 7;

#define FC_LOAD_TILE(K0) do { \
    _Pragma("unroll") \
    for (int p = 0; p < 32; p++) { \
        int row = wrow + p * 4, k = (K0) + wc0; \
        int ng = nbase + row; \
        wv[p] = (ng < 1000 && k < FCK) ? __ldg(&fcw[ng * FCK + k]) : 0.f; \
    } \
    _Pragma("unroll") \
    for (int p = 0; p < 4; p++) { \
        int b = frow + p * 32; \
        size_t idx = ((size_t)b * KPAD + (K0)) / 8 + fq; \
        fh[p] = g_fT_hi[idx]; \
        fl[p] = g_fT_lo[idx]; \
    } \
} while (0)

    FC_LOAD_TILE(sk * NCHUNK * 64);

    for (int it = 0; it < NCHUNK; it++) {
        __syncthreads();
        // convert + store current tile from registers
#pragma unroll
        for (int p = 0; p < 32; p++) {
            int row = wrow + p * 4, c = wc0;
            float v = wv[p];
            __nv_bfloat16 h = __float2bfloat16(v);
            __nv_bfloat16 l = __float2bfloat16(v - __bfloat162float(h));
            Wh[row * FPITCH + c] = h;
            Wl[row * FPITCH + c] = l;
        }
#pragma unroll
        for (int p = 0; p < 4; p++) {
            int b = frow + p * 32;
            *(uint4*)&Fh[b * FPITCH + fq * 8] = fh[p];
            *(uint4*)&Fl[b * FPITCH + fq * 8] = fl[p];
        }
        __syncthreads();
        if (it + 1 < NCHUNK) FC_LOAD_TILE((sk * NCHUNK + it + 1) * 64);

#pragma unroll
        for (int k16 = 0; k16 < 4; k16++) {
            uint32_t ak = (k16 * 16 + aKof) * 2;
            uint32_t ah[4], al[4];
            LDSM_X4(ah, base + WH_OFF + aRow * (FPITCH * 2) + ak);
            LDSM_X4(al, base + WL_OFF + aRow * (FPITCH * 2) + ak);
            uint32_t bk = (k16 * 16 + bKof) * 2;
#pragma unroll
            for (int bt2 = 0; bt2 < 8; bt2++) {
                uint32_t brow = bt2 * 16 + bRowB;
                uint32_t bh[4], bl[4];
                LDSM_X4(bh, base + FH_OFF + brow * (FPITCH * 2) + bk);
                LDSM_X4(bl, base + FL_OFF + brow * (FPITCH * 2) + bk);
                MMA_BF16(acc[2 * bt2],     ah, bh[0], bh[1]);
                MMA_BF16(acc[2 * bt2 + 1], ah, bh[2], bh[3]);
                MMA_BF16(acc[2 * bt2],     ah, bl[0], bl[1]);
                MMA_BF16(acc[2 * bt2 + 1], ah, bl[2], bl[3]);
                MMA_BF16(acc[2 * bt2],     al, bh[0], bh[1]);
                MMA_BF16(acc[2 * bt2 + 1], al, bh[2], bh[3]);
            }
        }
    }

    float* outp = g_part + sk * (BSZ * 1000);
    const int n0 = nbase + wid * 16 + g;
    const int n1 = n0 + 8;
#pragma unroll
    for (int bt = 0; bt < 16; bt++) {
        int b0 = bt * 8 + tg * 2;
        if (n0 < 1000) {
            outp[b0 * 1000 + n0]       = acc[bt][0];
            outp[(b0 + 1) * 1000 + n0] = acc[bt][1];
        }
        if (n1 < 1000) {
            outp[b0 * 1000 + n1]       = acc[bt][2];
            outp[(b0 + 1) * 1000 + n1] = acc[bt][3];
        }
    }
}

// ---------------------------------------------------------------------------
// reduce split-K partials (fixed order -> deterministic) + bias + softmax
// ---------------------------------------------------------------------------
__global__ void softmax_kernel(const float* __restrict__ fcb,
                               float* __restrict__ out) {
    int b = blockIdx.x, t = threadIdx.x;
    __shared__ float lg[1000];
    __shared__ float red[8];
    __shared__ float bc;

    for (int n = t; n < 1000; n += 256) {
        float v = fcb[n];
        for (int s = 0; s < SK2; s++) v += g_part[(s * BSZ + b) * 1000 + n];
        lg[n] = v;
    }
    __syncthreads();

    float mx = -3.4e38f;
    for (int n = t; n < 1000; n += 256) mx = fmaxf(mx, lg[n]);
    for (int o = 16; o; o >>= 1) mx = fmaxf(mx, __shfl_xor_sync(0xffffffffu, mx, o));
    if ((t & 31) == 0) red[t >> 5] = mx;
    __syncthreads();
    if (t == 0) {
        float m = red[0];
        for (int w = 1; w < 8; w++) m = fmaxf(m, red[w]);
        bc = m;
    }
    __syncthreads();
    mx = bc;

    float s = 0.f;
    for (int n = t; n < 1000; n += 256) s += expf(lg[n] - mx);
    for (int o = 16; o; o >>= 1) s += __shfl_xor_sync(0xffffffffu, s, o);
    __syncthreads();
    if ((t & 31) == 0) red[t >> 5] = s;
    __syncthreads();
    if (t == 0) {
        float tot = 0.f;
        for (int w = 0; w < 8; w++) tot += red[w];
        bc = 1.f / tot;
    }
    __syncthreads();
    float inv = bc;
    for (int n = t; n < 1000; n += 256)
        out[b * 1000 + n] = expf(lg[n] - mx) * inv;
}

// ---------------------------------------------------------------------------

extern "C" void kernel_launch(void* const* d_in, const int* in_sizes, int n_in,
                              void* d_out, int out_size) {
    const float* x   = (const float*)d_in[0];
    const float* w0  = (const float*)d_in[1];
    const float* b0  = (const float*)d_in[2];
    const float* g0  = (const float*)d_in[3];
    const float* be0 = (const float*)d_in[4];
    const float* w1  = (const float*)d_in[5];
    const float* b1  = (const float*)d_in[6];
    const float* g1  = (const float*)d_in[7];
    const float* be1 = (const float*)d_in[8];
    const float* fcw = (const float*)d_in[9];
    const float* fcb = (const float*)d_in[10];
    float* out = (float*)d_out;

    const int smem0 = 2 * 128 * CPB + 2 * 16 * CPB;                   // 115200 B
    cudaFuncSetAttribute(conv0_mma_kernel, cudaFuncAttributeMaxDynamicSharedMemorySize, smem0);
    const int smemFC = 4 * 128 * FPITCH * 2;                          // 73728 B
    cudaFuncSetAttribute(fc_mma_kernel, cudaFuncAttributeMaxDynamicSharedMemorySize, smemFC);

    conv0_mma_kernel<<<dim3(55, 55), 256, smem0>>>(x, w0, b0);
    ln2_kernel<<<128, 256>>>(0);
    norm_pool_kernel<<<(BSZ * 110 * 110 + 255) / 256, 256>>>(g0, be0);
    conv1_kernel<<<dim3(53, 53), 128>>>(w1, b1);
    ln2_kernel<<<128, 256>>>(1);
    norm1t_kernel<<<396, 256>>>(g1, be1);
    fc_mma_kernel<<<dim3(8, SK2), 256, smemFC>>>(fcw);
    softmax_kernel<<<128, 256>>>(fcb, out);
}